// round 6
// baseline (speedup 1.0000x reference)
#include <cuda_runtime.h>

// GraphSAGE on GB300 — 7 kernels:
//   K_init:  cnt=0; block0: dtype sniff + weight folding (W2l@Wc etc)
//   K_hist:  cnt[dst]++ (4 edges/thread)
//   K_scanL: per-1024-block local exclusive scan -> off, block sums
//   K_scanA: per-block prefix of block sums (warp reduce) + add; cur=off
//   K_fill:  csr[cur[dst]++] = src (4 edges/thread)
//   K_l1:    FUSED: gather neighbor-mean of x into smem tile, then
//            h = relu(agg@W1l + b1 + x@W1r); t = h@W2lc; r = h@W2rc
//            (64x64x64 tile, 4x4 microtiles, f32x2 mainloop)
//   K_final: out[i] = mean_{e:dst=i} t[src[e]] + r[i] + bc2

#define NMAX 100000
#define EMAX 1600000
#define NB_SCAN ((NMAX + 1023) / 1024)   // 98

__device__ float2 g_t[NMAX];
__device__ float2 g_r[NMAX];
__device__ int    g_cnt[NMAX];
__device__ int    g_off[NMAX + 1];
__device__ int    g_cur[NMAX];
__device__ int    g_csr[EMAX];
__device__ int    g_bsum[NB_SCAN];
__device__ float  g_W2lc[128];
__device__ float  g_W2rc[128];
__device__ float  g_bc2[2];
__device__ int    g_is64;

// ---- packed f32x2 helpers ------------------------------------------------
__device__ __forceinline__ unsigned long long pk2(float lo, float hi) {
    unsigned long long r;
    asm("mov.b64 %0, {%1, %2};" : "=l"(r) : "f"(lo), "f"(hi));
    return r;
}
__device__ __forceinline__ void fma2(unsigned long long& acc,
                                     unsigned long long a,
                                     unsigned long long b) {
    asm("fma.rn.f32x2 %0, %1, %2, %0;" : "+l"(acc) : "l"(a), "l"(b));
}
__device__ __forceinline__ float2 upk2(unsigned long long v) {
    float2 f;
    asm("mov.b64 {%0, %1}, %2;" : "=f"(f.x), "=f"(f.y) : "l"(v));
    return f;
}

__device__ __forceinline__ int edge_val(const int* __restrict__ w, int is64, int idx) {
    return is64 ? w[2 * idx] : w[idx];
}

// ---------------------------------------------------------------- K_init
__global__ void sage_init_kernel(const int* __restrict__ ei,
                                 const float* __restrict__ W2l,
                                 const float* __restrict__ b2,
                                 const float* __restrict__ W2r,
                                 const float* __restrict__ Wc,
                                 const float* __restrict__ bc,
                                 int n) {
    int i = blockIdx.x * blockDim.x + threadIdx.x;
    if (i < n) g_cnt[i] = 0;
    if (blockIdx.x == 0) {
        int t = threadIdx.x;
        if (t == 128) {                     // dtype sniff (int64 -> odd words 0)
            int odd_nonzero = 0;
#pragma unroll
            for (int j = 1; j < 64; j += 2)
                if (ei[j] != 0) odd_nonzero = 1;
            g_is64 = odd_nonzero ? 0 : 1;
        }
        if (t < 128) {                      // fold W2l@Wc, W2r@Wc
            int k = t >> 1, c = t & 1;
            float s = 0.f, sr = 0.f;
#pragma unroll
            for (int m = 0; m < 64; m++) {
                float w = Wc[m * 2 + c];
                s  += W2l[k * 64 + m] * w;
                sr += W2r[k * 64 + m] * w;
            }
            g_W2lc[k * 2 + c] = s;
            g_W2rc[k * 2 + c] = sr;
        }
        if (t < 2) {
            float sb = 0.f;
            for (int m = 0; m < 64; m++) sb += b2[m] * Wc[m * 2 + t];
            g_bc2[t] = sb + bc[t];
        }
    }
}

// ---------------------------------------------------------------- K_hist
__global__ void sage_hist_kernel(const int* __restrict__ ei, int E, int nn) {
    int base = (blockIdx.x * blockDim.x + threadIdx.x) * 4;
    int is64 = g_is64;
#pragma unroll
    for (int u = 0; u < 4; u++) {
        int e = base + u;
        if (e < E) {
            int dst = edge_val(ei, is64, E + e);
            if ((unsigned)dst < (unsigned)nn)
                atomicAdd(&g_cnt[dst], 1);
        }
    }
}

// ---------------------------------------------------------------- K_scanL
__global__ void sage_scan_local(int n) {
    __shared__ int wsum[32];
    int b = blockIdx.x;
    int t = threadIdx.x;
    int lane = t & 31, wid = t >> 5;
    int i = b * 1024 + t;
    int v = (i < n) ? g_cnt[i] : 0;
    int x = v;
#pragma unroll
    for (int d = 1; d < 32; d <<= 1) {
        int y = __shfl_up_sync(0xffffffffu, x, d);
        if (lane >= d) x += y;
    }
    if (lane == 31) wsum[wid] = x;
    __syncthreads();
    if (wid == 0) {
        int w = wsum[lane];
        int xw = w;
#pragma unroll
        for (int d = 1; d < 32; d <<= 1) {
            int y = __shfl_up_sync(0xffffffffu, xw, d);
            if (lane >= d) xw += y;
        }
        wsum[lane] = xw;
    }
    __syncthreads();
    int wexcl = (wid == 0) ? 0 : wsum[wid - 1];
    if (i < n) g_off[i] = (x - v) + wexcl;      // local exclusive
    if (t == 0) g_bsum[b] = wsum[31];            // block total
}

// ---------------------------------------------------------------- K_scanA (block prefix + add)
__global__ void sage_scan_add(int n, int nb) {
    __shared__ int pre_s;
    int b = blockIdx.x;
    int t = threadIdx.x;
    if (t < 32) {
        int pre = 0, tot = 0;
        for (int i = t; i < nb; i += 32) {
            int v = g_bsum[i];
            tot += v;
            if (i < b) pre += v;
        }
#pragma unroll
        for (int d = 16; d >= 1; d >>= 1) {
            pre += __shfl_xor_sync(0xffffffffu, pre, d);
            tot += __shfl_xor_sync(0xffffffffu, tot, d);
        }
        if (t == 0) {
            pre_s = pre;
            if (b == 0) g_off[n] = tot;
        }
    }
    __syncthreads();
    int i = b * 1024 + t;
    if (i < n) {
        int o = g_off[i] + pre_s;
        g_off[i] = o;
        g_cur[i] = o;
    }
}

// ---------------------------------------------------------------- K_fill
__global__ void sage_fill_kernel(const int* __restrict__ ei, int E, int nn) {
    int base = (blockIdx.x * blockDim.x + threadIdx.x) * 4;
    int is64 = g_is64;
#pragma unroll
    for (int u = 0; u < 4; u++) {
        int e = base + u;
        if (e < E) {
            int src = edge_val(ei, is64, e);
            int dst = edge_val(ei, is64, E + e);
            if ((unsigned)dst < (unsigned)nn && (unsigned)src < (unsigned)nn) {
                int p = atomicAdd(&g_cur[dst], 1);
                if ((unsigned)p < (unsigned)EMAX)
                    g_csr[p] = src;
            }
        }
    }
}

// ---------------------------------------------------------------- K_l1: fused gather + GEMMs + epilogue
// 64 nodes/block. Gather: 4 threads per node (kq=tid>>6), each accumulates
// 16 features (4 float4) of the neighbor mean, writes transposed smem tile.
// GEMM: 4x4 microtiles, f32x2 packed accumulate. Epilogue folds layer2+cls.
__global__ void __launch_bounds__(256) sage_layer1_kernel(
        const float* __restrict__ x,
        const float* __restrict__ W1l,
        const float* __restrict__ b1,
        const float* __restrict__ W1r,
        int nn) {
    __shared__ float Wl_s[4096];   // [k][n]
    __shared__ float Wr_s[4096];   // [k][n]
    __shared__ float A1_s[4096];   // [k][m] neighbor-mean tile (transposed)
    __shared__ float X_s[4096];    // [k][m] x tile (transposed)
    __shared__ float b1_s[64];
    __shared__ float Wlc_s[128];
    __shared__ float Wrc_s[128];

    int tid = threadIdx.x;
    for (int i = tid; i < 4096; i += 256) {
        Wl_s[i] = W1l[i];
        Wr_s[i] = W1r[i];
    }
    if (tid < 64)  b1_s[tid] = b1[tid];
    if (tid < 128) { Wlc_s[tid] = g_W2lc[tid]; Wrc_s[tid] = g_W2rc[tid]; }

    int m0 = blockIdx.x * 64;
    {
        int m  = tid & 63;           // node slot
        int kq = tid >> 6;           // feature quad-group 0..3 (16 floats each)
        int gm = m0 + m;
        float4 acc[4];
#pragma unroll
        for (int j = 0; j < 4; j++) acc[j] = make_float4(0.f, 0.f, 0.f, 0.f);
        float4 xr[4];
#pragma unroll
        for (int j = 0; j < 4; j++) xr[j] = make_float4(0.f, 0.f, 0.f, 0.f);

        if (gm < nn) {
            const float4* xrow = (const float4*)(x + (size_t)gm * 64);
#pragma unroll
            for (int j = 0; j < 4; j++) xr[j] = __ldg(xrow + kq * 4 + j);

            int s0 = g_off[gm], s1 = g_off[gm + 1];
            for (int e = s0; e < s1; e++) {
                int s = g_csr[e];
                const float4* nrow = (const float4*)(x + (size_t)s * 64);
#pragma unroll
                for (int j = 0; j < 4; j++) {
                    float4 v = __ldg(nrow + kq * 4 + j);
                    acc[j].x += v.x; acc[j].y += v.y;
                    acc[j].z += v.z; acc[j].w += v.w;
                }
            }
            float inv = 1.0f / fmaxf((float)(s1 - s0), 1.0f);
#pragma unroll
            for (int j = 0; j < 4; j++) {
                acc[j].x *= inv; acc[j].y *= inv;
                acc[j].z *= inv; acc[j].w *= inv;
            }
        }
#pragma unroll
        for (int j = 0; j < 4; j++) {
            int kb = (kq * 4 + j) * 4;
            A1_s[(kb + 0) * 64 + m] = acc[j].x; A1_s[(kb + 1) * 64 + m] = acc[j].y;
            A1_s[(kb + 2) * 64 + m] = acc[j].z; A1_s[(kb + 3) * 64 + m] = acc[j].w;
            X_s [(kb + 0) * 64 + m] = xr[j].x;  X_s [(kb + 1) * 64 + m] = xr[j].y;
            X_s [(kb + 2) * 64 + m] = xr[j].z;  X_s [(kb + 3) * 64 + m] = xr[j].w;
        }
    }
    __syncthreads();

    int n_idx = tid & 15;
    int m_idx = tid >> 4;
    unsigned long long acc2[4][2];
    unsigned long long z = pk2(0.f, 0.f);
#pragma unroll
    for (int i = 0; i < 4; i++) { acc2[i][0] = z; acc2[i][1] = z; }

#pragma unroll 16
    for (int k = 0; k < 64; k++) {
        float4 a  = *(const float4*)&A1_s[k * 64 + m_idx * 4];
        float4 xx = *(const float4*)&X_s [k * 64 + m_idx * 4];
        float4 wl = *(const float4*)&Wl_s[k * 64 + n_idx * 4];
        float4 wr = *(const float4*)&Wr_s[k * 64 + n_idx * 4];
        unsigned long long wl01 = pk2(wl.x, wl.y), wl23 = pk2(wl.z, wl.w);
        unsigned long long wr01 = pk2(wr.x, wr.y), wr23 = pk2(wr.z, wr.w);
        float av[4] = {a.x, a.y, a.z, a.w};
        float xv[4] = {xx.x, xx.y, xx.z, xx.w};
#pragma unroll
        for (int i = 0; i < 4; i++) {
            unsigned long long ab = pk2(av[i], av[i]);
            unsigned long long xb = pk2(xv[i], xv[i]);
            fma2(acc2[i][0], ab, wl01);
            fma2(acc2[i][0], xb, wr01);
            fma2(acc2[i][1], ab, wl23);
            fma2(acc2[i][1], xb, wr23);
        }
    }

#pragma unroll
    for (int i = 0; i < 4; i++) {
        float2 p0 = upk2(acc2[i][0]);
        float2 p1 = upk2(acc2[i][1]);
        float accv[4] = {p0.x, p0.y, p1.x, p1.y};
        float t0 = 0.f, t1 = 0.f, r0 = 0.f, r1 = 0.f;
#pragma unroll
        for (int j = 0; j < 4; j++) {
            int nj = n_idx * 4 + j;
            float h = fmaxf(accv[j] + b1_s[nj], 0.f);
            t0 += h * Wlc_s[nj * 2 + 0];
            t1 += h * Wlc_s[nj * 2 + 1];
            r0 += h * Wrc_s[nj * 2 + 0];
            r1 += h * Wrc_s[nj * 2 + 1];
        }
#pragma unroll
        for (int d = 8; d >= 1; d >>= 1) {
            t0 += __shfl_xor_sync(0xffffffffu, t0, d);
            t1 += __shfl_xor_sync(0xffffffffu, t1, d);
            r0 += __shfl_xor_sync(0xffffffffu, r0, d);
            r1 += __shfl_xor_sync(0xffffffffu, r1, d);
        }
        int gm = m0 + m_idx * 4 + i;
        if (n_idx == 0 && gm < nn) {
            g_t[gm] = make_float2(t0, t1);
            g_r[gm] = make_float2(r0, r1);
        }
    }
}

// ---------------------------------------------------------------- K_final
__global__ void sage_final_kernel(float2* __restrict__ out, int nn) {
    int i = blockIdx.x * blockDim.x + threadIdx.x;
    if (i >= nn) return;
    int s0 = g_off[i], s1 = g_off[i + 1];
    float a0 = 0.f, a1 = 0.f, b0 = 0.f, b1v = 0.f;
    int e = s0;
    for (; e + 1 < s1; e += 2) {
        int sA = g_csr[e], sB = g_csr[e + 1];
        float2 vA = g_t[sA];
        float2 vB = g_t[sB];
        a0 += vA.x; a1 += vA.y;
        b0 += vB.x; b1v += vB.y;
    }
    if (e < s1) {
        float2 vA = g_t[g_csr[e]];
        a0 += vA.x; a1 += vA.y;
    }
    float inv = 1.0f / fmaxf((float)(s1 - s0), 1.0f);
    float2 rv = g_r[i];
    out[i] = make_float2((a0 + b0) * inv + rv.x + g_bc2[0],
                         (a1 + b1v) * inv + rv.y + g_bc2[1]);
}

// ---------------------------------------------------------------- launch
extern "C" void kernel_launch(void* const* d_in, const int* in_sizes, int n_in,
                              void* d_out, int out_size) {
    const float* x   = (const float*)d_in[0];
    const int*   ei  = (const int*)d_in[1];     // int32 or int64 (auto-detected)
    const float* W1l = (const float*)d_in[2];
    const float* b1  = (const float*)d_in[3];
    const float* W1r = (const float*)d_in[4];
    const float* W2l = (const float*)d_in[5];
    const float* b2  = (const float*)d_in[6];
    const float* W2r = (const float*)d_in[7];
    const float* Wc  = (const float*)d_in[8];
    const float* bc  = (const float*)d_in[9];

    int nn = in_sizes[0] / 64;
    int E  = in_sizes[1] / 2;
    if (nn > NMAX) nn = NMAX;
    if (E > EMAX)  E = EMAX;
    int nb = (nn + 1023) / 1024;

    sage_init_kernel<<<(nn + 255) / 256, 256>>>(ei, W2l, b2, W2r, Wc, bc, nn);
    sage_hist_kernel<<<(E / 4 + 255) / 256, 256>>>(ei, E, nn);
    sage_scan_local<<<nb, 1024>>>(nn);
    sage_scan_add<<<nb, 1024>>>(nn, nb);
    sage_fill_kernel<<<(E / 4 + 255) / 256, 256>>>(ei, E, nn);
    sage_layer1_kernel<<<(nn + 63) / 64, 256>>>(x, W1l, b1, W1r, nn);
    sage_final_kernel<<<(nn + 255) / 256, 256>>>((float2*)d_out, nn);
}

// round 7
// speedup vs baseline: 1.1091x; 1.1091x over previous
#include <cuda_runtime.h>

// GraphSAGE on GB300 — 5 kernels (layer1 deliberately placed at launch #4 for ncu):
//   K1 hist:  cnt[dst]++ (4 edges/thr); block0 also folds W2l@Wc, W2r@Wc, bc2
//             (cnt is zero from static init / re-zeroed by K5 each call)
//   K2 scan:  single-pass exclusive scan (local scan + decoupled lookback,
//             98 blocks all resident in wave 1) -> off, cur
//   K3 fill:  csr[cur[dst]++] = src (4 edges/thr)
//   K4 layer1 FUSED: gather neighbor-mean of x into smem tile, then
//             h = relu(agg@W1l + b1 + x@W1r); t = h@W2lc; r = h@W2rc
//             128 thr, 64x64x64 tile, 8x4 microtiles, one accumulator
//   K5 final: out[i] = mean_{e:dst=i} t[src[e]] + r[i] + bc2; re-zero cnt/flags

#define NMAX 100000
#define EMAX 1600000
#define NB_SCAN ((NMAX + 1023) / 1024)   // 98

__device__ float2 g_t[NMAX];
__device__ float2 g_r[NMAX];
__device__ int    g_cnt[NMAX];           // zero-init; re-zeroed by K5
__device__ int    g_off[NMAX + 1];
__device__ int    g_cur[NMAX];
__device__ int    g_csr[EMAX];
__device__ int    g_bsum[NB_SCAN];
__device__ volatile int g_bflag[NB_SCAN]; // zero-init; re-zeroed by K5
__device__ float  g_W2lc[128];
__device__ float  g_W2rc[128];
__device__ float  g_bc2[2];

__device__ __forceinline__ int edge_val(const int* __restrict__ w, int is64, int idx) {
    return is64 ? w[2 * idx] : w[idx];   // int64 little-endian low word, or int32
}
// int64 (values < 2^31) => odd 32-bit words all zero. int32 random => not.
__device__ __forceinline__ int sniff64(const int* __restrict__ w) {
    int odd = 0;
#pragma unroll
    for (int j = 1; j < 64; j += 2) odd |= w[j];
    return odd == 0;
}

// ---------------------------------------------------------------- K1: hist + fold
__global__ void sage_hist_kernel(const int* __restrict__ ei, int E, int nn,
                                 const float* __restrict__ W2l,
                                 const float* __restrict__ b2,
                                 const float* __restrict__ W2r,
                                 const float* __restrict__ Wc,
                                 const float* __restrict__ bc) {
    __shared__ int s_is64;
    int t = threadIdx.x;
    if (t == 0) s_is64 = sniff64(ei);
    __syncthreads();
    int is64 = s_is64;

    if (blockIdx.x == 0) {               // weight folding (independent of edges)
        if (t < 128) {
            int k = t >> 1, c = t & 1;
            float s = 0.f, sr = 0.f;
#pragma unroll
            for (int m = 0; m < 64; m++) {
                float w = Wc[m * 2 + c];
                s  += W2l[k * 64 + m] * w;
                sr += W2r[k * 64 + m] * w;
            }
            g_W2lc[k * 2 + c] = s;
            g_W2rc[k * 2 + c] = sr;
        }
        if (t < 2) {
            float sb = 0.f;
            for (int m = 0; m < 64; m++) sb += b2[m] * Wc[m * 2 + t];
            g_bc2[t] = sb + bc[t];
        }
    }

    int base = (blockIdx.x * blockDim.x + t) * 4;
#pragma unroll
    for (int u = 0; u < 4; u++) {
        int e = base + u;
        if (e < E) {
            int dst = edge_val(ei, is64, E + e);
            if ((unsigned)dst < (unsigned)nn)
                atomicAdd(&g_cnt[dst], 1);
        }
    }
}

// ---------------------------------------------------------------- K2: single-pass scan
__global__ void sage_scan_kernel(int n, int nb) {
    __shared__ int wsum[32];
    __shared__ int pre_s;
    int b = blockIdx.x;
    int t = threadIdx.x;
    int lane = t & 31, wid = t >> 5;
    int i = b * 1024 + t;
    int v = (i < n) ? g_cnt[i] : 0;
    int x = v;
#pragma unroll
    for (int d = 1; d < 32; d <<= 1) {
        int y = __shfl_up_sync(0xffffffffu, x, d);
        if (lane >= d) x += y;
    }
    if (lane == 31) wsum[wid] = x;
    __syncthreads();
    if (wid == 0) {
        int w = wsum[lane];
        int xw = w;
#pragma unroll
        for (int d = 1; d < 32; d <<= 1) {
            int y = __shfl_up_sync(0xffffffffu, xw, d);
            if (lane >= d) xw += y;
        }
        wsum[lane] = xw;
    }
    __syncthreads();
    int total = wsum[31];
    // publish aggregate (before any spinning -> no deadlock)
    if (t == 0) {
        pre_s = 0;
        g_bsum[b] = total;
        __threadfence();
        g_bflag[b] = 1;
    }
    __syncthreads();
    // lookback: thread t (< b) waits for block t's aggregate, accumulates
    if (t < b) {
        while (g_bflag[t] == 0) {}
        __threadfence();
        atomicAdd(&pre_s, g_bsum[t]);
    }
    __syncthreads();
    int pre = pre_s;
    int wexcl = (wid == 0) ? 0 : wsum[wid - 1];
    if (i < n) {
        int o = pre + (x - v) + wexcl;
        g_off[i] = o;
        g_cur[i] = o;
    }
    if (b == nb - 1 && t == 0) g_off[n] = pre + total;
}

// ---------------------------------------------------------------- K3: fill
__global__ void sage_fill_kernel(const int* __restrict__ ei, int E, int nn) {
    __shared__ int s_is64;
    if (threadIdx.x == 0) s_is64 = sniff64(ei);
    __syncthreads();
    int is64 = s_is64;
    int base = (blockIdx.x * blockDim.x + threadIdx.x) * 4;
#pragma unroll
    for (int u = 0; u < 4; u++) {
        int e = base + u;
        if (e < E) {
            int src = edge_val(ei, is64, e);
            int dst = edge_val(ei, is64, E + e);
            if ((unsigned)dst < (unsigned)nn && (unsigned)src < (unsigned)nn) {
                int p = atomicAdd(&g_cur[dst], 1);
                if ((unsigned)p < (unsigned)EMAX)
                    g_csr[p] = src;
            }
        }
    }
}

// ---------------------------------------------------------------- K4: fused gather + GEMM + epilogue
// 128 threads, 64 nodes/block. Gather: 2 thr/node, 32 features each (8 float4,
// MLP=8). GEMM: 8x4 microtiles, ONE accumulator for agg@W1l + x@W1r.
__global__ void __launch_bounds__(128) sage_layer1_kernel(
        const float* __restrict__ x,
        const float* __restrict__ W1l,
        const float* __restrict__ b1,
        const float* __restrict__ W1r,
        int nn) {
    __shared__ float Wl_s[4096];   // [k][n]
    __shared__ float Wr_s[4096];   // [k][n]
    __shared__ float A_s[4096];    // [k][m] neighbor-mean (transposed)
    __shared__ float X_s[4096];    // [k][m] x (transposed)
    __shared__ float b1_s[64];
    __shared__ float Wlc_s[128];
    __shared__ float Wrc_s[128];

    int tid = threadIdx.x;
    for (int i = tid; i < 4096; i += 128) {
        Wl_s[i] = W1l[i];
        Wr_s[i] = W1r[i];
    }
    if (tid < 64)  b1_s[tid] = b1[tid];
    if (tid < 128) { Wlc_s[tid] = g_W2lc[tid]; Wrc_s[tid] = g_W2rc[tid]; }

    int m0 = blockIdx.x * 64;
    {   // gather phase
        int m = tid >> 1, half = tid & 1;
        int gm = m0 + m;
        float4 acc[8], xr[8];
#pragma unroll
        for (int j = 0; j < 8; j++) {
            acc[j] = make_float4(0.f, 0.f, 0.f, 0.f);
            xr[j]  = make_float4(0.f, 0.f, 0.f, 0.f);
        }
        if (gm < nn) {
            const float4* xrow = (const float4*)(x + (size_t)gm * 64) + half * 8;
#pragma unroll
            for (int j = 0; j < 8; j++) xr[j] = __ldg(xrow + j);
            int s0 = g_off[gm], s1 = g_off[gm + 1];
            for (int e = s0; e < s1; e++) {
                const float4* nr = (const float4*)(x + (size_t)g_csr[e] * 64) + half * 8;
#pragma unroll
                for (int j = 0; j < 8; j++) {
                    float4 vv = __ldg(nr + j);
                    acc[j].x += vv.x; acc[j].y += vv.y;
                    acc[j].z += vv.z; acc[j].w += vv.w;
                }
            }
            float inv = 1.0f / fmaxf((float)(s1 - s0), 1.0f);
#pragma unroll
            for (int j = 0; j < 8; j++) {
                acc[j].x *= inv; acc[j].y *= inv;
                acc[j].z *= inv; acc[j].w *= inv;
            }
        }
#pragma unroll
        for (int j = 0; j < 8; j++) {
            int kb = (half * 8 + j) * 4;   // k = half*32 + j*4 + c
            A_s[(kb + 0) * 64 + m] = acc[j].x; A_s[(kb + 1) * 64 + m] = acc[j].y;
            A_s[(kb + 2) * 64 + m] = acc[j].z; A_s[(kb + 3) * 64 + m] = acc[j].w;
            X_s[(kb + 0) * 64 + m] = xr[j].x;  X_s[(kb + 1) * 64 + m] = xr[j].y;
            X_s[(kb + 2) * 64 + m] = xr[j].z;  X_s[(kb + 3) * 64 + m] = xr[j].w;
        }
    }
    __syncthreads();

    // GEMM phase: n_idx 0..15 (4 cols), m_oct 0..7 (8 rows)
    int n_idx = tid & 15;
    int m_oct = tid >> 4;
    float acc[8][4];
#pragma unroll
    for (int i = 0; i < 8; i++)
#pragma unroll
        for (int j = 0; j < 4; j++) acc[i][j] = 0.f;

#pragma unroll 8
    for (int k = 0; k < 64; k++) {
        float4 wl = *(const float4*)&Wl_s[k * 64 + n_idx * 4];
        float4 wr = *(const float4*)&Wr_s[k * 64 + n_idx * 4];
        float4 a0 = *(const float4*)&A_s[k * 64 + m_oct * 8];
        float4 a1 = *(const float4*)&A_s[k * 64 + m_oct * 8 + 4];
        float4 x0 = *(const float4*)&X_s[k * 64 + m_oct * 8];
        float4 x1 = *(const float4*)&X_s[k * 64 + m_oct * 8 + 4];
        float av[8] = {a0.x, a0.y, a0.z, a0.w, a1.x, a1.y, a1.z, a1.w};
        float xv[8] = {x0.x, x0.y, x0.z, x0.w, x1.x, x1.y, x1.z, x1.w};
        float wlv[4] = {wl.x, wl.y, wl.z, wl.w};
        float wrv[4] = {wr.x, wr.y, wr.z, wr.w};
#pragma unroll
        for (int i = 0; i < 8; i++)
#pragma unroll
            for (int j = 0; j < 4; j++)
                acc[i][j] += av[i] * wlv[j] + xv[i] * wrv[j];
    }

    // epilogue: fold layer2 + classifier, reduce across the 16 n_idx lanes
#pragma unroll
    for (int i = 0; i < 8; i++) {
        float t0 = 0.f, t1 = 0.f, r0 = 0.f, r1 = 0.f;
#pragma unroll
        for (int j = 0; j < 4; j++) {
            int nj = n_idx * 4 + j;
            float h = fmaxf(acc[i][j] + b1_s[nj], 0.f);
            t0 += h * Wlc_s[nj * 2 + 0];
            t1 += h * Wlc_s[nj * 2 + 1];
            r0 += h * Wrc_s[nj * 2 + 0];
            r1 += h * Wrc_s[nj * 2 + 1];
        }
#pragma unroll
        for (int d = 8; d >= 1; d >>= 1) {   // xor within 16-lane groups
            t0 += __shfl_xor_sync(0xffffffffu, t0, d);
            t1 += __shfl_xor_sync(0xffffffffu, t1, d);
            r0 += __shfl_xor_sync(0xffffffffu, r0, d);
            r1 += __shfl_xor_sync(0xffffffffu, r1, d);
        }
        int gm = m0 + m_oct * 8 + i;
        if (n_idx == 0 && gm < nn) {
            g_t[gm] = make_float2(t0, t1);
            g_r[gm] = make_float2(r0, r1);
        }
    }
}

// ---------------------------------------------------------------- K5: final (+ state reset for next call)
__global__ void sage_final_kernel(float2* __restrict__ out, int nn) {
    int i = blockIdx.x * blockDim.x + threadIdx.x;
    if (blockIdx.x == 0 && threadIdx.x < NB_SCAN) g_bflag[threadIdx.x] = 0;
    if (i >= nn) return;
    g_cnt[i] = 0;                            // restore for next replay
    int s0 = g_off[i], s1 = g_off[i + 1];
    float a0 = 0.f, a1 = 0.f, b0 = 0.f, b1v = 0.f;
    int e = s0;
    for (; e + 1 < s1; e += 2) {
        float2 vA = g_t[g_csr[e]];
        float2 vB = g_t[g_csr[e + 1]];
        a0 += vA.x; a1 += vA.y;
        b0 += vB.x; b1v += vB.y;
    }
    if (e < s1) {
        float2 vA = g_t[g_csr[e]];
        a0 += vA.x; a1 += vA.y;
    }
    float inv = 1.0f / fmaxf((float)(s1 - s0), 1.0f);
    float2 rv = g_r[i];
    out[i] = make_float2((a0 + b0) * inv + rv.x + g_bc2[0],
                         (a1 + b1v) * inv + rv.y + g_bc2[1]);
}

// ---------------------------------------------------------------- launch
extern "C" void kernel_launch(void* const* d_in, const int* in_sizes, int n_in,
                              void* d_out, int out_size) {
    const float* x   = (const float*)d_in[0];
    const int*   ei  = (const int*)d_in[1];     // int32 or int64 (auto-detected)
    const float* W1l = (const float*)d_in[2];
    const float* b1  = (const float*)d_in[3];
    const float* W1r = (const float*)d_in[4];
    const float* W2l = (const float*)d_in[5];
    const float* b2  = (const float*)d_in[6];
    const float* W2r = (const float*)d_in[7];
    const float* Wc  = (const float*)d_in[8];
    const float* bc  = (const float*)d_in[9];

    int nn = in_sizes[0] / 64;
    int E  = in_sizes[1] / 2;
    if (nn > NMAX) nn = NMAX;
    if (E > EMAX)  E = EMAX;
    int nb = (nn + 1023) / 1024;

    sage_hist_kernel<<<(E / 4 + 255) / 256, 256>>>(ei, E, nn, W2l, b2, W2r, Wc, bc);
    sage_scan_kernel<<<nb, 1024>>>(nn, nb);
    sage_fill_kernel<<<(E / 4 + 255) / 256, 256>>>(ei, E, nn);
    sage_layer1_kernel<<<(nn + 63) / 64, 128>>>(x, W1l, b1, W1r, nn);   // launch #4
    sage_final_kernel<<<(nn + 255) / 256, 256>>>((float2*)d_out, nn);
}

// round 9
// speedup vs baseline: 1.2426x; 1.1204x over previous
#include <cuda_runtime.h>

// GraphSAGE on GB300 — 5 kernels (layer1 at launch #4 for ncu):
//   K1 hist:  cnt[dst]++ (4 edges/thr); block0 also folds W2l@Wc, W2r@Wc, bc2
//   K2 scan:  single-pass exclusive scan (decoupled lookback, 98 blocks)
//   K3 fill:  csr[cur[dst]++] = src
//   K4 layer1 FUSED: coalesced 16-thr/node gather of neighbor means (full
//             128B-line wavefronts) into XOR-swizzled smem tiles, then
//             h = relu(agg@W1l + b1 + x@W1r); t = h@W2lc; r = h@W2rc
//             (128 thr, 64x64x64 tile, 8x4 microtiles)
//   K5 final: out[i] = mean_{e:dst=i} t[src[e]] + r[i] + bc2; reset state

#define NMAX 100000
#define EMAX 1600000
#define NB_SCAN ((NMAX + 1023) / 1024)   // 98

__device__ float2 g_t[NMAX];
__device__ float2 g_r[NMAX];
__device__ int    g_cnt[NMAX];           // zero-init; re-zeroed by K5
__device__ int    g_off[NMAX + 1];
__device__ int    g_cur[NMAX];
__device__ int    g_csr[EMAX];
__device__ int    g_bsum[NB_SCAN];
__device__ volatile int g_bflag[NB_SCAN]; // zero-init; re-zeroed by K5
__device__ float  g_W2lc[128];
__device__ float  g_W2rc[128];
__device__ float  g_bc2[2];

__device__ __forceinline__ int edge_val(const int* __restrict__ w, int is64, int idx) {
    return is64 ? w[2 * idx] : w[idx];   // int64 little-endian low word, or int32
}
__device__ __forceinline__ int sniff64(const int* __restrict__ w) {
    int odd = 0;
#pragma unroll
    for (int j = 1; j < 64; j += 2) odd |= w[j];
    return odd == 0;
}

// ---------------------------------------------------------------- K1: hist + fold
__global__ void sage_hist_kernel(const int* __restrict__ ei, int E, int nn,
                                 const float* __restrict__ W2l,
                                 const float* __restrict__ b2,
                                 const float* __restrict__ W2r,
                                 const float* __restrict__ Wc,
                                 const float* __restrict__ bc) {
    __shared__ int s_is64;
    int t = threadIdx.x;
    if (t == 0) s_is64 = sniff64(ei);
    __syncthreads();
    int is64 = s_is64;

    if (blockIdx.x == 0) {
        if (t < 128) {
            int k = t >> 1, c = t & 1;
            float s = 0.f, sr = 0.f;
#pragma unroll
            for (int m = 0; m < 64; m++) {
                float w = Wc[m * 2 + c];
                s  += W2l[k * 64 + m] * w;
                sr += W2r[k * 64 + m] * w;
            }
            g_W2lc[k * 2 + c] = s;
            g_W2rc[k * 2 + c] = sr;
        }
        if (t < 2) {
            float sb = 0.f;
            for (int m = 0; m < 64; m++) sb += b2[m] * Wc[m * 2 + t];
            g_bc2[t] = sb + bc[t];
        }
    }

    int base = (blockIdx.x * blockDim.x + t) * 4;
#pragma unroll
    for (int u = 0; u < 4; u++) {
        int e = base + u;
        if (e < E) {
            int dst = edge_val(ei, is64, E + e);
            if ((unsigned)dst < (unsigned)nn)
                atomicAdd(&g_cnt[dst], 1);
        }
    }
}

// ---------------------------------------------------------------- K2: single-pass scan
__global__ void sage_scan_kernel(int n, int nb) {
    __shared__ int wsum[32];
    __shared__ int pre_s;
    int b = blockIdx.x;
    int t = threadIdx.x;
    int lane = t & 31, wid = t >> 5;
    int i = b * 1024 + t;
    int v = (i < n) ? g_cnt[i] : 0;
    int x = v;
#pragma unroll
    for (int d = 1; d < 32; d <<= 1) {
        int y = __shfl_up_sync(0xffffffffu, x, d);
        if (lane >= d) x += y;
    }
    if (lane == 31) wsum[wid] = x;
    __syncthreads();
    if (wid == 0) {
        int w = wsum[lane];
        int xw = w;
#pragma unroll
        for (int d = 1; d < 32; d <<= 1) {
            int y = __shfl_up_sync(0xffffffffu, xw, d);
            if (lane >= d) xw += y;
        }
        wsum[lane] = xw;
    }
    __syncthreads();
    int total = wsum[31];
    if (t == 0) {
        pre_s = 0;
        g_bsum[b] = total;
        __threadfence();
        g_bflag[b] = 1;
    }
    __syncthreads();
    if (t < b) {
        while (g_bflag[t] == 0) {}
        __threadfence();
        atomicAdd(&pre_s, g_bsum[t]);
    }
    __syncthreads();
    int pre = pre_s;
    int wexcl = (wid == 0) ? 0 : wsum[wid - 1];
    if (i < n) {
        int o = pre + (x - v) + wexcl;
        g_off[i] = o;
        g_cur[i] = o;
    }
    if (b == nb - 1 && t == 0) g_off[n] = pre + total;
}

// ---------------------------------------------------------------- K3: fill
__global__ void sage_fill_kernel(const int* __restrict__ ei, int E, int nn) {
    __shared__ int s_is64;
    if (threadIdx.x == 0) s_is64 = sniff64(ei);
    __syncthreads();
    int is64 = s_is64;
    int base = (blockIdx.x * blockDim.x + threadIdx.x) * 4;
#pragma unroll
    for (int u = 0; u < 4; u++) {
        int e = base + u;
        if (e < E) {
            int src = edge_val(ei, is64, e);
            int dst = edge_val(ei, is64, E + e);
            if ((unsigned)dst < (unsigned)nn && (unsigned)src < (unsigned)nn) {
                int p = atomicAdd(&g_cur[dst], 1);
                if ((unsigned)p < (unsigned)EMAX)
                    g_csr[p] = src;
            }
        }
    }
}

// ---------------------------------------------------------------- K4: fused gather + GEMM + epilogue
// Gather: 16 thr/node, lane c owns float4 chunk c -> every LDG.128 warp
// instruction covers 2 full node rows (4x 128B lines, 100% wavefront eff).
// Smem tiles are [k][64] with a 4-float-group XOR swizzle (g ^= (k>>2)&7)
// so the transposed scalar STS is conflict-light and GEMM float4 reads stay
// broadcast. GEMM: 8x4 microtiles, one accumulator for agg@W1l + x@W1r.
__global__ void __launch_bounds__(128) sage_layer1_kernel(
        const float* __restrict__ x,
        const float* __restrict__ W1l,
        const float* __restrict__ b1,
        const float* __restrict__ W1r,
        int nn) {
    __shared__ float Wl_s[4096];   // [k][n]
    __shared__ float Wr_s[4096];   // [k][n]
    __shared__ float A_s[4096];    // [k][m] swizzled
    __shared__ float X_s[4096];    // [k][m] swizzled
    __shared__ float b1_s[64];
    __shared__ float Wlc_s[128];
    __shared__ float Wrc_s[128];

    int tid = threadIdx.x;
    for (int i = tid; i < 4096; i += 128) {
        Wl_s[i] = W1l[i];
        Wr_s[i] = W1r[i];
    }
    if (tid < 64)  b1_s[tid] = b1[tid];
    if (tid < 128) { Wlc_s[tid] = g_W2lc[tid]; Wrc_s[tid] = g_W2rc[tid]; }

    int m0 = blockIdx.x * 64;
    {   // ---- gather phase: 8 passes x 8 nodes, 16 threads per node
        int c  = tid & 15;          // float4 chunk of the 64-float row
        int pn = tid >> 4;          // 0..7
        int kb = c * 4;             // k rows written: kb..kb+3
        int sw = c & 7;             // = (k>>2)&7 for these rows
#pragma unroll 1
        for (int p = 0; p < 8; p++) {
            int m  = p * 8 + pn;
            int gm = m0 + m;
            float4 acc = make_float4(0.f, 0.f, 0.f, 0.f);
            float4 xr  = make_float4(0.f, 0.f, 0.f, 0.f);
            if (gm < nn) {
                xr = __ldg((const float4*)(x + (size_t)gm * 64) + c);
                int s0 = g_off[gm], s1 = g_off[gm + 1];
                int e = s0;
                for (; e + 4 <= s1; e += 4) {
                    int i0 = g_csr[e + 0], i1 = g_csr[e + 1];
                    int i2 = g_csr[e + 2], i3 = g_csr[e + 3];
                    float4 v0 = __ldg((const float4*)(x + (size_t)i0 * 64) + c);
                    float4 v1 = __ldg((const float4*)(x + (size_t)i1 * 64) + c);
                    float4 v2 = __ldg((const float4*)(x + (size_t)i2 * 64) + c);
                    float4 v3 = __ldg((const float4*)(x + (size_t)i3 * 64) + c);
                    acc.x += v0.x + v1.x + v2.x + v3.x;
                    acc.y += v0.y + v1.y + v2.y + v3.y;
                    acc.z += v0.z + v1.z + v2.z + v3.z;
                    acc.w += v0.w + v1.w + v2.w + v3.w;
                }
                for (; e < s1; e++) {
                    float4 v = __ldg((const float4*)(x + (size_t)g_csr[e] * 64) + c);
                    acc.x += v.x; acc.y += v.y; acc.z += v.z; acc.w += v.w;
                }
                float inv = 1.0f / fmaxf((float)(s1 - s0), 1.0f);
                acc.x *= inv; acc.y *= inv; acc.z *= inv; acc.w *= inv;
            }
            int col = (((m >> 2) ^ sw) << 2) + (m & 3);   // swizzled column
            A_s[(kb + 0) * 64 + col] = acc.x;
            A_s[(kb + 1) * 64 + col] = acc.y;
            A_s[(kb + 2) * 64 + col] = acc.z;
            A_s[(kb + 3) * 64 + col] = acc.w;
            X_s[(kb + 0) * 64 + col] = xr.x;
            X_s[(kb + 1) * 64 + col] = xr.y;
            X_s[(kb + 2) * 64 + col] = xr.z;
            X_s[(kb + 3) * 64 + col] = xr.w;
        }
    }
    __syncthreads();

    // ---- GEMM phase: n_idx 0..15 (4 outputs), m_oct 0..7 (8 nodes)
    int n_idx = tid & 15;
    int m_oct = tid >> 4;
    float acc[8][4];
#pragma unroll
    for (int i = 0; i < 8; i++)
#pragma unroll
        for (int j = 0; j < 4; j++) acc[i][j] = 0.f;

#pragma unroll 8
    for (int k = 0; k < 64; k++) {
        int sw = (k >> 2) & 7;
        int g0 = (m_oct * 2) ^ sw;
        int g1 = (m_oct * 2 + 1) ^ sw;
        float4 wl = *(const float4*)&Wl_s[k * 64 + n_idx * 4];
        float4 wr = *(const float4*)&Wr_s[k * 64 + n_idx * 4];
        float4 a0 = *(const float4*)&A_s[k * 64 + g0 * 4];
        float4 a1 = *(const float4*)&A_s[k * 64 + g1 * 4];
        float4 x0 = *(const float4*)&X_s[k * 64 + g0 * 4];
        float4 x1 = *(const float4*)&X_s[k * 64 + g1 * 4];
        float av[8] = {a0.x, a0.y, a0.z, a0.w, a1.x, a1.y, a1.z, a1.w};
        float xv[8] = {x0.x, x0.y, x0.z, x0.w, x1.x, x1.y, x1.z, x1.w};
        float wlv[4] = {wl.x, wl.y, wl.z, wl.w};
        float wrv[4] = {wr.x, wr.y, wr.z, wr.w};
#pragma unroll
        for (int i = 0; i < 8; i++)
#pragma unroll
            for (int j = 0; j < 4; j++)
                acc[i][j] += av[i] * wlv[j] + xv[i] * wrv[j];
    }

    // ---- epilogue: fold layer2 + classifier, reduce across 16 n_idx lanes
#pragma unroll
    for (int i = 0; i < 8; i++) {
        float t0 = 0.f, t1 = 0.f, r0 = 0.f, r1 = 0.f;
#pragma unroll
        for (int j = 0; j < 4; j++) {
            int nj = n_idx * 4 + j;
            float h = fmaxf(acc[i][j] + b1_s[nj], 0.f);
            t0 += h * Wlc_s[nj * 2 + 0];
            t1 += h * Wlc_s[nj * 2 + 1];
            r0 += h * Wrc_s[nj * 2 + 0];
            r1 += h * Wrc_s[nj * 2 + 1];
        }
#pragma unroll
        for (int d = 8; d >= 1; d >>= 1) {
            t0 += __shfl_xor_sync(0xffffffffu, t0, d);
            t1 += __shfl_xor_sync(0xffffffffu, t1, d);
            r0 += __shfl_xor_sync(0xffffffffu, r0, d);
            r1 += __shfl_xor_sync(0xffffffffu, r1, d);
        }
        int gm = m0 + m_oct * 8 + i;
        if (n_idx == 0 && gm < nn) {
            g_t[gm] = make_float2(t0, t1);
            g_r[gm] = make_float2(r0, r1);
        }
    }
}

// ---------------------------------------------------------------- K5: final (+ state reset)
__global__ void sage_final_kernel(float2* __restrict__ out, int nn) {
    int i = blockIdx.x * blockDim.x + threadIdx.x;
    if (blockIdx.x == 0 && threadIdx.x < NB_SCAN) g_bflag[threadIdx.x] = 0;
    if (i >= nn) return;
    g_cnt[i] = 0;                            // restore for next replay
    int s0 = g_off[i], s1 = g_off[i + 1];
    float a0 = 0.f, a1 = 0.f, b0 = 0.f, b1v = 0.f;
    int e = s0;
    for (; e + 1 < s1; e += 2) {
        float2 vA = g_t[g_csr[e]];
        float2 vB = g_t[g_csr[e + 1]];
        a0 += vA.x; a1 += vA.y;
        b0 += vB.x; b1v += vB.y;
    }
    if (e < s1) {
        float2 vA = g_t[g_csr[e]];
        a0 += vA.x; a1 += vA.y;
    }
    float inv = 1.0f / fmaxf((float)(s1 - s0), 1.0f);
    float2 rv = g_r[i];
    out[i] = make_float2((a0 + b0) * inv + rv.x + g_bc2[0],
                         (a1 + b1v) * inv + rv.y + g_bc2[1]);
}

// ---------------------------------------------------------------- launch
extern "C" void kernel_launch(void* const* d_in, const int* in_sizes, int n_in,
                              void* d_out, int out_size) {
    const float* x   = (const float*)d_in[0];
    const int*   ei  = (const int*)d_in[1];     // int32 or int64 (auto-detected)
    const float* W1l = (const float*)d_in[2];
    const float* b1  = (const float*)d_in[3];
    const float* W1r = (const float*)d_in[4];
    const float* W2l = (const float*)d_in[5];
    const float* b2  = (const float*)d_in[6];
    const float* W2r = (const float*)d_in[7];
    const float* Wc  = (const float*)d_in[8];
    const float* bc  = (const float*)d_in[9];

    int nn = in_sizes[0] / 64;
    int E  = in_sizes[1] / 2;
    if (nn > NMAX) nn = NMAX;
    if (E > EMAX)  E = EMAX;
    int nb = (nn + 1023) / 1024;

    sage_hist_kernel<<<(E / 4 + 255) / 256, 256>>>(ei, E, nn, W2l, b2, W2r, Wc, bc);
    sage_scan_kernel<<<nb, 1024>>>(nn, nb);
    sage_fill_kernel<<<(E / 4 + 255) / 256, 256>>>(ei, E, nn);
    sage_layer1_kernel<<<(nn + 63) / 64, 128>>>(x, W1l, b1, W1r, nn);   // launch #4
    sage_final_kernel<<<(nn + 255) / 256, 256>>>((float2*)d_out, nn);
}

// round 11
// speedup vs baseline: 1.5745x; 1.2671x over previous
#include <cuda_runtime.h>

// GraphSAGE on GB300 — 5 kernels (layer1 at launch #4 for ncu):
//   K1 hist:  cnt[dst]++ (4 edges/thr); block0 also folds W2l@Wc, W2r@Wc, bc2
//   K2 scan:  single-pass exclusive scan (decoupled lookback, 98 blocks)
//   K3 fill:  csr[cur[dst]++] = src
//   K4 layer1 FUSED: coalesced 16-thr/node gather of neighbor means into
//             XOR-swizzled smem tiles; GEMM reads W1l/W1r straight from L1
//             (no smem W tiles -> 34KB smem -> 6 blocks/SM, 24 warps).
//             h = relu(agg@W1l + b1 + x@W1r); t = h@W2lc; r = h@W2rc
//   K5 final: out[i] = mean_{e:dst=i} t[src[e]] + r[i] + bc2; reset state

#define NMAX 100000
#define EMAX 1600000
#define NB_SCAN ((NMAX + 1023) / 1024)   // 98

__device__ float2 g_t[NMAX];
__device__ float2 g_r[NMAX];
__device__ int    g_cnt[NMAX];           // zero-init; re-zeroed by K5
__device__ int    g_off[NMAX + 1];
__device__ int    g_cur[NMAX];
__device__ int    g_csr[EMAX];
__device__ int    g_bsum[NB_SCAN];
__device__ volatile int g_bflag[NB_SCAN]; // zero-init; re-zeroed by K5
__device__ float  g_W2lc[128];
__device__ float  g_W2rc[128];
__device__ float  g_bc2[2];

__device__ __forceinline__ int edge_val(const int* __restrict__ w, int is64, int idx) {
    return is64 ? w[2 * idx] : w[idx];   // int64 little-endian low word, or int32
}
__device__ __forceinline__ int sniff64(const int* __restrict__ w) {
    int odd = 0;
#pragma unroll
    for (int j = 1; j < 64; j += 2) odd |= w[j];
    return odd == 0;
}

// ---------------------------------------------------------------- K1: hist + fold
__global__ void sage_hist_kernel(const int* __restrict__ ei, int E, int nn,
                                 const float* __restrict__ W2l,
                                 const float* __restrict__ b2,
                                 const float* __restrict__ W2r,
                                 const float* __restrict__ Wc,
                                 const float* __restrict__ bc) {
    __shared__ int s_is64;
    int t = threadIdx.x;
    if (t == 0) s_is64 = sniff64(ei);
    __syncthreads();
    int is64 = s_is64;

    if (blockIdx.x == 0) {
        if (t < 128) {
            int k = t >> 1, c = t & 1;
            float s = 0.f, sr = 0.f;
#pragma unroll
            for (int m = 0; m < 64; m++) {
                float w = Wc[m * 2 + c];
                s  += W2l[k * 64 + m] * w;
                sr += W2r[k * 64 + m] * w;
            }
            g_W2lc[k * 2 + c] = s;
            g_W2rc[k * 2 + c] = sr;
        }
        if (t < 2) {
            float sb = 0.f;
            for (int m = 0; m < 64; m++) sb += b2[m] * Wc[m * 2 + t];
            g_bc2[t] = sb + bc[t];
        }
    }

    int base = (blockIdx.x * blockDim.x + t) * 4;
#pragma unroll
    for (int u = 0; u < 4; u++) {
        int e = base + u;
        if (e < E) {
            int dst = edge_val(ei, is64, E + e);
            if ((unsigned)dst < (unsigned)nn)
                atomicAdd(&g_cnt[dst], 1);
        }
    }
}

// ---------------------------------------------------------------- K2: single-pass scan
__global__ void sage_scan_kernel(int n, int nb) {
    __shared__ int wsum[32];
    __shared__ int pre_s;
    int b = blockIdx.x;
    int t = threadIdx.x;
    int lane = t & 31, wid = t >> 5;
    int i = b * 1024 + t;
    int v = (i < n) ? g_cnt[i] : 0;
    int x = v;
#pragma unroll
    for (int d = 1; d < 32; d <<= 1) {
        int y = __shfl_up_sync(0xffffffffu, x, d);
        if (lane >= d) x += y;
    }
    if (lane == 31) wsum[wid] = x;
    __syncthreads();
    if (wid == 0) {
        int w = wsum[lane];
        int xw = w;
#pragma unroll
        for (int d = 1; d < 32; d <<= 1) {
            int y = __shfl_up_sync(0xffffffffu, xw, d);
            if (lane >= d) xw += y;
        }
        wsum[lane] = xw;
    }
    __syncthreads();
    int total = wsum[31];
    if (t == 0) {
        pre_s = 0;
        g_bsum[b] = total;
        __threadfence();
        g_bflag[b] = 1;
    }
    __syncthreads();
    if (t < b) {
        while (g_bflag[t] == 0) {}
        __threadfence();
        atomicAdd(&pre_s, g_bsum[t]);
    }
    __syncthreads();
    int pre = pre_s;
    int wexcl = (wid == 0) ? 0 : wsum[wid - 1];
    if (i < n) {
        int o = pre + (x - v) + wexcl;
        g_off[i] = o;
        g_cur[i] = o;
    }
    if (b == nb - 1 && t == 0) g_off[n] = pre + total;
}

// ---------------------------------------------------------------- K3: fill
__global__ void sage_fill_kernel(const int* __restrict__ ei, int E, int nn) {
    __shared__ int s_is64;
    if (threadIdx.x == 0) s_is64 = sniff64(ei);
    __syncthreads();
    int is64 = s_is64;
    int base = (blockIdx.x * blockDim.x + threadIdx.x) * 4;
#pragma unroll
    for (int u = 0; u < 4; u++) {
        int e = base + u;
        if (e < E) {
            int src = edge_val(ei, is64, e);
            int dst = edge_val(ei, is64, E + e);
            if ((unsigned)dst < (unsigned)nn && (unsigned)src < (unsigned)nn) {
                int p = atomicAdd(&g_cur[dst], 1);
                if ((unsigned)p < (unsigned)EMAX)
                    g_csr[p] = src;
            }
        }
    }
}

// ---------------------------------------------------------------- K4: fused gather + GEMM + epilogue
// Gather: 16 thr/node, lane c owns float4 chunk c (full-line wavefronts),
// tiles XOR-swizzled (group g ^= (k>>2)&7). GEMM: 8x4 microtiles; W1l/W1r
// read via __ldg (L1-resident across 1563 blocks) instead of smem so the
// block fits 34KB smem -> 6 blocks/SM (vs 3) for latency hiding.
__global__ void __launch_bounds__(128, 6) sage_layer1_kernel(
        const float* __restrict__ x,
        const float* __restrict__ W1l,
        const float* __restrict__ b1,
        const float* __restrict__ W1r,
        int nn) {
    __shared__ float A_s[4096];    // [k][m] swizzled neighbor-mean tile
    __shared__ float X_s[4096];    // [k][m] swizzled x tile
    __shared__ float b1_s[64];
    __shared__ float Wlc_s[128];
    __shared__ float Wrc_s[128];

    int tid = threadIdx.x;
    if (tid < 64)  b1_s[tid] = b1[tid];
    if (tid < 128) { Wlc_s[tid] = g_W2lc[tid]; Wrc_s[tid] = g_W2rc[tid]; }

    int m0 = blockIdx.x * 64;
    {   // ---- gather phase: 8 passes x 8 nodes, 16 threads per node
        int c  = tid & 15;          // float4 chunk of the 64-float row
        int pn = tid >> 4;          // 0..7
        int kb = c * 4;             // k rows written: kb..kb+3
        int sw = c & 7;             // = (k>>2)&7 for these rows
#pragma unroll 1
        for (int p = 0; p < 8; p++) {
            int m  = p * 8 + pn;
            int gm = m0 + m;
            float4 acc = make_float4(0.f, 0.f, 0.f, 0.f);
            float4 xr  = make_float4(0.f, 0.f, 0.f, 0.f);
            if (gm < nn) {
                xr = __ldg((const float4*)(x + (size_t)gm * 64) + c);
                int s0 = g_off[gm], s1 = g_off[gm + 1];
                int e = s0;
                for (; e + 4 <= s1; e += 4) {
                    int i0 = g_csr[e + 0], i1 = g_csr[e + 1];
                    int i2 = g_csr[e + 2], i3 = g_csr[e + 3];
                    float4 v0 = __ldg((const float4*)(x + (size_t)i0 * 64) + c);
                    float4 v1 = __ldg((const float4*)(x + (size_t)i1 * 64) + c);
                    float4 v2 = __ldg((const float4*)(x + (size_t)i2 * 64) + c);
                    float4 v3 = __ldg((const float4*)(x + (size_t)i3 * 64) + c);
                    acc.x += v0.x + v1.x + v2.x + v3.x;
                    acc.y += v0.y + v1.y + v2.y + v3.y;
                    acc.z += v0.z + v1.z + v2.z + v3.z;
                    acc.w += v0.w + v1.w + v2.w + v3.w;
                }
                for (; e < s1; e++) {
                    float4 v = __ldg((const float4*)(x + (size_t)g_csr[e] * 64) + c);
                    acc.x += v.x; acc.y += v.y; acc.z += v.z; acc.w += v.w;
                }
                float inv = 1.0f / fmaxf((float)(s1 - s0), 1.0f);
                acc.x *= inv; acc.y *= inv; acc.z *= inv; acc.w *= inv;
            }
            int col = (((m >> 2) ^ sw) << 2) + (m & 3);   // swizzled column
            A_s[(kb + 0) * 64 + col] = acc.x;
            A_s[(kb + 1) * 64 + col] = acc.y;
            A_s[(kb + 2) * 64 + col] = acc.z;
            A_s[(kb + 3) * 64 + col] = acc.w;
            X_s[(kb + 0) * 64 + col] = xr.x;
            X_s[(kb + 1) * 64 + col] = xr.y;
            X_s[(kb + 2) * 64 + col] = xr.z;
            X_s[(kb + 3) * 64 + col] = xr.w;
        }
    }
    __syncthreads();

    // ---- GEMM phase: n_idx 0..15 (4 outputs), m_oct 0..7 (8 nodes)
    int n_idx = tid & 15;
    int m_oct = tid >> 4;
    float acc[8][4];
#pragma unroll
    for (int i = 0; i < 8; i++)
#pragma unroll
        for (int j = 0; j < 4; j++) acc[i][j] = 0.f;

    const float4* Wl4 = (const float4*)W1l;
    const float4* Wr4 = (const float4*)W1r;

#pragma unroll 4
    for (int k4 = 0; k4 < 16; k4++) {       // groups of 4 k
        int sw = k4 & 7;
        int g0 = (m_oct * 2) ^ sw;
        int g1 = (m_oct * 2 + 1) ^ sw;
#pragma unroll
        for (int kk = 0; kk < 4; kk++) {
            int k = k4 * 4 + kk;
            float4 wl = __ldg(Wl4 + k * 16 + n_idx);
            float4 wr = __ldg(Wr4 + k * 16 + n_idx);
            float4 a0 = *(const float4*)&A_s[k * 64 + g0 * 4];
            float4 a1 = *(const float4*)&A_s[k * 64 + g1 * 4];
            float4 x0 = *(const float4*)&X_s[k * 64 + g0 * 4];
            float4 x1 = *(const float4*)&X_s[k * 64 + g1 * 4];
            float av[8] = {a0.x, a0.y, a0.z, a0.w, a1.x, a1.y, a1.z, a1.w};
            float xv[8] = {x0.x, x0.y, x0.z, x0.w, x1.x, x1.y, x1.z, x1.w};
            float wlv[4] = {wl.x, wl.y, wl.z, wl.w};
            float wrv[4] = {wr.x, wr.y, wr.z, wr.w};
#pragma unroll
            for (int i = 0; i < 8; i++)
#pragma unroll
                for (int j = 0; j < 4; j++)
                    acc[i][j] += av[i] * wlv[j] + xv[i] * wrv[j];
        }
    }

    // ---- epilogue: fold layer2 + classifier, reduce across 16 n_idx lanes
#pragma unroll
    for (int i = 0; i < 8; i++) {
        float t0 = 0.f, t1 = 0.f, r0 = 0.f, r1 = 0.f;
#pragma unroll
        for (int j = 0; j < 4; j++) {
            int nj = n_idx * 4 + j;
            float h = fmaxf(acc[i][j] + b1_s[nj], 0.f);
            t0 += h * Wlc_s[nj * 2 + 0];
            t1 += h * Wlc_s[nj * 2 + 1];
            r0 += h * Wrc_s[nj * 2 + 0];
            r1 += h * Wrc_s[nj * 2 + 1];
        }
#pragma unroll
        for (int d = 8; d >= 1; d >>= 1) {
            t0 += __shfl_xor_sync(0xffffffffu, t0, d);
            t1 += __shfl_xor_sync(0xffffffffu, t1, d);
            r0 += __shfl_xor_sync(0xffffffffu, r0, d);
            r1 += __shfl_xor_sync(0xffffffffu, r1, d);
        }
        int gm = m0 + m_oct * 8 + i;
        if (n_idx == 0 && gm < nn) {
            g_t[gm] = make_float2(t0, t1);
            g_r[gm] = make_float2(r0, r1);
        }
    }
}

// ---------------------------------------------------------------- K5: final (+ state reset)
__global__ void sage_final_kernel(float2* __restrict__ out, int nn) {
    int i = blockIdx.x * blockDim.x + threadIdx.x;
    if (blockIdx.x == 0 && threadIdx.x < NB_SCAN) g_bflag[threadIdx.x] = 0;
    if (i >= nn) return;
    g_cnt[i] = 0;                            // restore for next replay
    int s0 = g_off[i], s1 = g_off[i + 1];
    float a0 = 0.f, a1 = 0.f, b0 = 0.f, b1v = 0.f;
    int e = s0;
    for (; e + 1 < s1; e += 2) {
        float2 vA = g_t[g_csr[e]];
        float2 vB = g_t[g_csr[e + 1]];
        a0 += vA.x; a1 += vA.y;
        b0 += vB.x; b1v += vB.y;
    }
    if (e < s1) {
        float2 vA = g_t[g_csr[e]];
        a0 += vA.x; a1 += vA.y;
    }
    float inv = 1.0f / fmaxf((float)(s1 - s0), 1.0f);
    float2 rv = g_r[i];
    out[i] = make_float2((a0 + b0) * inv + rv.x + g_bc2[0],
                         (a1 + b1v) * inv + rv.y + g_bc2[1]);
}

// ---------------------------------------------------------------- launch
extern "C" void kernel_launch(void* const* d_in, const int* in_sizes, int n_in,
                              void* d_out, int out_size) {
    const float* x   = (const float*)d_in[0];
    const int*   ei  = (const int*)d_in[1];     // int32 or int64 (auto-detected)
    const float* W1l = (const float*)d_in[2];
    const float* b1  = (const float*)d_in[3];
    const float* W1r = (const float*)d_in[4];
    const float* W2l = (const float*)d_in[5];
    const float* b2  = (const float*)d_in[6];
    const float* W2r = (const float*)d_in[7];
    const float* Wc  = (const float*)d_in[8];
    const float* bc  = (const float*)d_in[9];

    int nn = in_sizes[0] / 64;
    int E  = in_sizes[1] / 2;
    if (nn > NMAX) nn = NMAX;
    if (E > EMAX)  E = EMAX;
    int nb = (nn + 1023) / 1024;

    sage_hist_kernel<<<(E / 4 + 255) / 256, 256>>>(ei, E, nn, W2l, b2, W2r, Wc, bc);
    sage_scan_kernel<<<nb, 1024>>>(nn, nb);
    sage_fill_kernel<<<(E / 4 + 255) / 256, 256>>>(ei, E, nn);
    sage_layer1_kernel<<<(nn + 63) / 64, 128>>>(x, W1l, b1, W1r, nn);   // launch #4
    sage_final_kernel<<<(nn + 255) / 256, 256>>>((float2*)d_out, nn);
}

// round 12
// speedup vs baseline: 1.7120x; 1.0873x over previous
#include <cuda_runtime.h>

// GraphSAGE on GB300 — 5 kernels (layer1 at launch #4 for ncu):
//   K1 hist:  cnt[dst]++ (4 edges/thr); block0 also folds W2l@Wc, W2r@Wc, bc2
//   K2 scan:  single-pass exclusive scan (decoupled lookback, 98 blocks)
//   K3 fill:  csr[cur[dst]++] = src
//   K4 layer1 FUSED: coalesced 16-thr/node gather of neighbor means into
//             XOR-swizzled smem tiles; GEMM reads W1l/W1r from L1.
//             256 thr/block, 34KB smem, 4 blocks/SM -> 32 warps (occ 50%).
//             h = relu(agg@W1l + b1 + x@W1r); t = h@W2lc; r = h@W2rc
//   K5 final: out[i] = mean_{e:dst=i} t[src[e]] + r[i] + bc2; reset state

#define NMAX 100000
#define EMAX 1600000
#define NB_SCAN ((NMAX + 1023) / 1024)   // 98

__device__ float2 g_t[NMAX];
__device__ float2 g_r[NMAX];
__device__ int    g_cnt[NMAX];           // zero-init; re-zeroed by K5
__device__ int    g_off[NMAX + 1];
__device__ int    g_cur[NMAX];
__device__ int    g_csr[EMAX];
__device__ int    g_bsum[NB_SCAN];
__device__ volatile int g_bflag[NB_SCAN]; // zero-init; re-zeroed by K5
__device__ float  g_W2lc[128];
__device__ float  g_W2rc[128];
__device__ float  g_bc2[2];

__device__ __forceinline__ int edge_val(const int* __restrict__ w, int is64, int idx) {
    return is64 ? w[2 * idx] : w[idx];   // int64 little-endian low word, or int32
}
__device__ __forceinline__ int sniff64(const int* __restrict__ w) {
    int odd = 0;
#pragma unroll
    for (int j = 1; j < 64; j += 2) odd |= w[j];
    return odd == 0;
}

// ---------------------------------------------------------------- K1: hist + fold
__global__ void sage_hist_kernel(const int* __restrict__ ei, int E, int nn,
                                 const float* __restrict__ W2l,
                                 const float* __restrict__ b2,
                                 const float* __restrict__ W2r,
                                 const float* __restrict__ Wc,
                                 const float* __restrict__ bc) {
    __shared__ int s_is64;
    int t = threadIdx.x;
    if (t == 0) s_is64 = sniff64(ei);
    __syncthreads();
    int is64 = s_is64;

    if (blockIdx.x == 0) {
        if (t < 128) {
            int k = t >> 1, c = t & 1;
            float s = 0.f, sr = 0.f;
#pragma unroll
            for (int m = 0; m < 64; m++) {
                float w = Wc[m * 2 + c];
                s  += W2l[k * 64 + m] * w;
                sr += W2r[k * 64 + m] * w;
            }
            g_W2lc[k * 2 + c] = s;
            g_W2rc[k * 2 + c] = sr;
        }
        if (t < 2) {
            float sb = 0.f;
            for (int m = 0; m < 64; m++) sb += b2[m] * Wc[m * 2 + t];
            g_bc2[t] = sb + bc[t];
        }
    }

    int base = (blockIdx.x * blockDim.x + t) * 4;
#pragma unroll
    for (int u = 0; u < 4; u++) {
        int e = base + u;
        if (e < E) {
            int dst = edge_val(ei, is64, E + e);
            if ((unsigned)dst < (unsigned)nn)
                atomicAdd(&g_cnt[dst], 1);
        }
    }
}

// ---------------------------------------------------------------- K2: single-pass scan
__global__ void sage_scan_kernel(int n, int nb) {
    __shared__ int wsum[32];
    __shared__ int pre_s;
    int b = blockIdx.x;
    int t = threadIdx.x;
    int lane = t & 31, wid = t >> 5;
    int i = b * 1024 + t;
    int v = (i < n) ? g_cnt[i] : 0;
    int x = v;
#pragma unroll
    for (int d = 1; d < 32; d <<= 1) {
        int y = __shfl_up_sync(0xffffffffu, x, d);
        if (lane >= d) x += y;
    }
    if (lane == 31) wsum[wid] = x;
    __syncthreads();
    if (wid == 0) {
        int w = wsum[lane];
        int xw = w;
#pragma unroll
        for (int d = 1; d < 32; d <<= 1) {
            int y = __shfl_up_sync(0xffffffffu, xw, d);
            if (lane >= d) xw += y;
        }
        wsum[lane] = xw;
    }
    __syncthreads();
    int total = wsum[31];
    if (t == 0) {
        pre_s = 0;
        g_bsum[b] = total;
        __threadfence();
        g_bflag[b] = 1;
    }
    __syncthreads();
    if (t < b) {
        while (g_bflag[t] == 0) {}
        __threadfence();
        atomicAdd(&pre_s, g_bsum[t]);
    }
    __syncthreads();
    int pre = pre_s;
    int wexcl = (wid == 0) ? 0 : wsum[wid - 1];
    if (i < n) {
        int o = pre + (x - v) + wexcl;
        g_off[i] = o;
        g_cur[i] = o;
    }
    if (b == nb - 1 && t == 0) g_off[n] = pre + total;
}

// ---------------------------------------------------------------- K3: fill
__global__ void sage_fill_kernel(const int* __restrict__ ei, int E, int nn) {
    __shared__ int s_is64;
    if (threadIdx.x == 0) s_is64 = sniff64(ei);
    __syncthreads();
    int is64 = s_is64;
    int base = (blockIdx.x * blockDim.x + threadIdx.x) * 4;
#pragma unroll
    for (int u = 0; u < 4; u++) {
        int e = base + u;
        if (e < E) {
            int src = edge_val(ei, is64, e);
            int dst = edge_val(ei, is64, E + e);
            if ((unsigned)dst < (unsigned)nn && (unsigned)src < (unsigned)nn) {
                int p = atomicAdd(&g_cur[dst], 1);
                if ((unsigned)p < (unsigned)EMAX)
                    g_csr[p] = src;
            }
        }
    }
}

// ---------------------------------------------------------------- K4: fused gather + GEMM + epilogue
// 256 threads, 64-node tile. Gather: 16 thr/node (lane c owns float4 chunk c,
// full-line wavefronts), 4 passes of 16 nodes, XOR-swizzled smem tiles
// (group g ^= (k>>2)&7). GEMM: 4x4 microtiles, W1l/W1r via __ldg (L1-resident
// across 1563 blocks). 34KB smem + 64-reg cap -> 4 blocks/SM = 32 warps.
__global__ void __launch_bounds__(256, 4) sage_layer1_kernel(
        const float* __restrict__ x,
        const float* __restrict__ W1l,
        const float* __restrict__ b1,
        const float* __restrict__ W1r,
        int nn) {
    __shared__ float A_s[4096];    // [k][m] swizzled neighbor-mean tile
    __shared__ float X_s[4096];    // [k][m] swizzled x tile
    __shared__ float b1_s[64];
    __shared__ float Wlc_s[128];
    __shared__ float Wrc_s[128];

    int tid = threadIdx.x;
    if (tid < 64)  b1_s[tid] = b1[tid];
    if (tid >= 64 && tid < 192) {
        Wlc_s[tid - 64] = g_W2lc[tid - 64];
        Wrc_s[tid - 64] = g_W2rc[tid - 64];
    }

    int m0 = blockIdx.x * 64;
    {   // ---- gather phase: 4 passes x 16 nodes, 16 threads per node
        int c  = tid & 15;          // float4 chunk of the 64-float row
        int pn = tid >> 4;          // 0..15
        int kb = c * 4;             // k rows written: kb..kb+3
        int sw = c & 7;             // = (k>>2)&7 for these rows
#pragma unroll 1
        for (int p = 0; p < 4; p++) {
            int m  = p * 16 + pn;
            int gm = m0 + m;
            float4 acc = make_float4(0.f, 0.f, 0.f, 0.f);
            float4 xr  = make_float4(0.f, 0.f, 0.f, 0.f);
            if (gm < nn) {
                xr = __ldg((const float4*)(x + (size_t)gm * 64) + c);
                int s0 = g_off[gm], s1 = g_off[gm + 1];
                int e = s0;
                for (; e + 4 <= s1; e += 4) {
                    int i0 = g_csr[e + 0], i1 = g_csr[e + 1];
                    int i2 = g_csr[e + 2], i3 = g_csr[e + 3];
                    float4 v0 = __ldg((const float4*)(x + (size_t)i0 * 64) + c);
                    float4 v1 = __ldg((const float4*)(x + (size_t)i1 * 64) + c);
                    float4 v2 = __ldg((const float4*)(x + (size_t)i2 * 64) + c);
                    float4 v3 = __ldg((const float4*)(x + (size_t)i3 * 64) + c);
                    acc.x += v0.x + v1.x + v2.x + v3.x;
                    acc.y += v0.y + v1.y + v2.y + v3.y;
                    acc.z += v0.z + v1.z + v2.z + v3.z;
                    acc.w += v0.w + v1.w + v2.w + v3.w;
                }
                for (; e < s1; e++) {
                    float4 v = __ldg((const float4*)(x + (size_t)g_csr[e] * 64) + c);
                    acc.x += v.x; acc.y += v.y; acc.z += v.z; acc.w += v.w;
                }
                float inv = 1.0f / fmaxf((float)(s1 - s0), 1.0f);
                acc.x *= inv; acc.y *= inv; acc.z *= inv; acc.w *= inv;
            }
            int col = (((m >> 2) ^ sw) << 2) + (m & 3);   // swizzled column
            A_s[(kb + 0) * 64 + col] = acc.x;
            A_s[(kb + 1) * 64 + col] = acc.y;
            A_s[(kb + 2) * 64 + col] = acc.z;
            A_s[(kb + 3) * 64 + col] = acc.w;
            X_s[(kb + 0) * 64 + col] = xr.x;
            X_s[(kb + 1) * 64 + col] = xr.y;
            X_s[(kb + 2) * 64 + col] = xr.z;
            X_s[(kb + 3) * 64 + col] = xr.w;
        }
    }
    __syncthreads();

    // ---- GEMM phase: n_idx 0..15 (4 outputs), m_idx 0..15 (4 nodes)
    int n_idx = tid & 15;
    int m_idx = tid >> 4;
    float acc[4][4];
#pragma unroll
    for (int i = 0; i < 4; i++)
#pragma unroll
        for (int j = 0; j < 4; j++) acc[i][j] = 0.f;

    const float4* Wl4 = (const float4*)W1l;
    const float4* Wr4 = (const float4*)W1r;

#pragma unroll 4
    for (int k4 = 0; k4 < 16; k4++) {       // groups of 4 k
        int g = (m_idx ^ (k4 & 7)) * 4;     // swizzled node-group base
#pragma unroll
        for (int kk = 0; kk < 4; kk++) {
            int k = k4 * 4 + kk;
            float4 wl = __ldg(Wl4 + k * 16 + n_idx);
            float4 wr = __ldg(Wr4 + k * 16 + n_idx);
            float4 a0 = *(const float4*)&A_s[k * 64 + g];
            float4 x0 = *(const float4*)&X_s[k * 64 + g];
            float av[4] = {a0.x, a0.y, a0.z, a0.w};
            float xv[4] = {x0.x, x0.y, x0.z, x0.w};
            float wlv[4] = {wl.x, wl.y, wl.z, wl.w};
            float wrv[4] = {wr.x, wr.y, wr.z, wr.w};
#pragma unroll
            for (int i = 0; i < 4; i++)
#pragma unroll
                for (int j = 0; j < 4; j++)
                    acc[i][j] += av[i] * wlv[j] + xv[i] * wrv[j];
        }
    }

    // ---- epilogue: fold layer2 + classifier, reduce across 16 n_idx lanes
#pragma unroll
    for (int i = 0; i < 4; i++) {
        float t0 = 0.f, t1 = 0.f, r0 = 0.f, r1 = 0.f;
#pragma unroll
        for (int j = 0; j < 4; j++) {
            int nj = n_idx * 4 + j;
            float h = fmaxf(acc[i][j] + b1_s[nj], 0.f);
            t0 += h * Wlc_s[nj * 2 + 0];
            t1 += h * Wlc_s[nj * 2 + 1];
            r0 += h * Wrc_s[nj * 2 + 0];
            r1 += h * Wrc_s[nj * 2 + 1];
        }
#pragma unroll
        for (int d = 8; d >= 1; d >>= 1) {   // reduce within 16-lane groups
            t0 += __shfl_xor_sync(0xffffffffu, t0, d);
            t1 += __shfl_xor_sync(0xffffffffu, t1, d);
            r0 += __shfl_xor_sync(0xffffffffu, r0, d);
            r1 += __shfl_xor_sync(0xffffffffu, r1, d);
        }
        int gm = m0 + m_idx * 4 + i;
        if (n_idx == 0 && gm < nn) {
            g_t[gm] = make_float2(t0, t1);
            g_r[gm] = make_float2(r0, r1);
        }
    }
}

// ---------------------------------------------------------------- K5: final (+ state reset)
__global__ void sage_final_kernel(float2* __restrict__ out, int nn) {
    int i = blockIdx.x * blockDim.x + threadIdx.x;
    if (blockIdx.x == 0 && threadIdx.x < NB_SCAN) g_bflag[threadIdx.x] = 0;
    if (i >= nn) return;
    g_cnt[i] = 0;                            // restore for next replay
    int s0 = g_off[i], s1 = g_off[i + 1];
    float a0 = 0.f, a1 = 0.f, b0 = 0.f, b1v = 0.f;
    int e = s0;
    for (; e + 1 < s1; e += 2) {
        float2 vA = g_t[g_csr[e]];
        float2 vB = g_t[g_csr[e + 1]];
        a0 += vA.x; a1 += vA.y;
        b0 += vB.x; b1v += vB.y;
    }
    if (e < s1) {
        float2 vA = g_t[g_csr[e]];
        a0 += vA.x; a1 += vA.y;
    }
    float inv = 1.0f / fmaxf((float)(s1 - s0), 1.0f);
    float2 rv = g_r[i];
    out[i] = make_float2((a0 + b0) * inv + rv.x + g_bc2[0],
                         (a1 + b1v) * inv + rv.y + g_bc2[1]);
}

// ---------------------------------------------------------------- launch
extern "C" void kernel_launch(void* const* d_in, const int* in_sizes, int n_in,
                              void* d_out, int out_size) {
    const float* x   = (const float*)d_in[0];
    const int*   ei  = (const int*)d_in[1];     // int32 or int64 (auto-detected)
    const float* W1l = (const float*)d_in[2];
    const float* b1  = (const float*)d_in[3];
    const float* W1r = (const float*)d_in[4];
    const float* W2l = (const float*)d_in[5];
    const float* b2  = (const float*)d_in[6];
    const float* W2r = (const float*)d_in[7];
    const float* Wc  = (const float*)d_in[8];
    const float* bc  = (const float*)d_in[9];

    int nn = in_sizes[0] / 64;
    int E  = in_sizes[1] / 2;
    if (nn > NMAX) nn = NMAX;
    if (E > EMAX)  E = EMAX;
    int nb = (nn + 1023) / 1024;

    sage_hist_kernel<<<(E / 4 + 255) / 256, 256>>>(ei, E, nn, W2l, b2, W2r, Wc, bc);
    sage_scan_kernel<<<nb, 1024>>>(nn, nb);
    sage_fill_kernel<<<(E / 4 + 255) / 256, 256>>>(ei, E, nn);
    sage_layer1_kernel<<<(nn + 63) / 64, 256>>>(x, W1l, b1, W1r, nn);   // launch #4
    sage_final_kernel<<<(nn + 255) / 256, 256>>>((float2*)d_out, nn);
}

// round 13
// speedup vs baseline: 2.0587x; 1.2026x over previous
#include <cuda_runtime.h>

// GraphSAGE on GB300 — 5 kernels (layer1 at launch #4 for ncu):
//   K1 hist:  cnt[dst]++ ; block0 folds W2l@Wc/W2r@Wc/bc2 AND packs
//             [W1l;W1r] into tf32 mma B-fragment order (g_Wfrag)
//   K2 scan:  single-pass exclusive scan (decoupled lookback)
//   K3 fill:  csr[cur[dst]++] = src
//   K4 layer1 FUSED: coalesced 16-thr/node gather of neighbor means into an
//             [m][k] smem tile (tf32-rounded, A|X concat k=128), then
//             mma.sync.m16n8k8.tf32 GEMM (8 warps: 4 m-tiles x 2 n-halves),
//             epilogue folds layer2+classifier, cross-warp combine in smem.
//   K5 final: out[i] = mean_{e:dst=i} t[src[e]] + r[i] + bc2; reset state

#define NMAX 100000
#define EMAX 1600000
#define NB_SCAN ((NMAX + 1023) / 1024)   // 98
#define S_STRIDE 132                      // 128 k + 4 pad (conflict-free frags)

__device__ float2 g_t[NMAX];
__device__ float2 g_r[NMAX];
__device__ int    g_cnt[NMAX];           // zero-init; re-zeroed by K5
__device__ int    g_off[NMAX + 1];
__device__ int    g_cur[NMAX];
__device__ int    g_csr[EMAX];
__device__ int    g_bsum[NB_SCAN];
__device__ volatile int g_bflag[NB_SCAN]; // zero-init; re-zeroed by K5
__device__ float2 g_Wfrag[16 * 8 * 32];   // [kstep][ntile][lane] tf32 B frags
__device__ float  g_W2lc[128];
__device__ float  g_W2rc[128];
__device__ float  g_bc2[2];

__device__ __forceinline__ int edge_val(const int* __restrict__ w, int is64, int idx) {
    return is64 ? w[2 * idx] : w[idx];   // int64 little-endian low word, or int32
}
__device__ __forceinline__ int sniff64(const int* __restrict__ w) {
    int odd = 0;
#pragma unroll
    for (int j = 1; j < 64; j += 2) odd |= w[j];
    return odd == 0;
}
__device__ __forceinline__ unsigned tf32r(float f) {
    unsigned u;
    asm("cvt.rna.tf32.f32 %0, %1;" : "=r"(u) : "f"(f));
    return u;
}
__device__ __forceinline__ void mma_tf32(float* c, unsigned a0, unsigned a1,
                                         unsigned a2, unsigned a3,
                                         unsigned b0, unsigned b1) {
    asm("mma.sync.aligned.m16n8k8.row.col.f32.tf32.tf32.f32 "
        "{%0,%1,%2,%3}, {%4,%5,%6,%7}, {%8,%9}, {%0,%1,%2,%3};"
        : "+f"(c[0]), "+f"(c[1]), "+f"(c[2]), "+f"(c[3])
        : "r"(a0), "r"(a1), "r"(a2), "r"(a3), "r"(b0), "r"(b1));
}

// ---------------------------------------------------------------- K1: hist + fold + Wfrag pack
__global__ void sage_hist_kernel(const int* __restrict__ ei, int E, int nn,
                                 const float* __restrict__ W1l,
                                 const float* __restrict__ W1r,
                                 const float* __restrict__ W2l,
                                 const float* __restrict__ b2,
                                 const float* __restrict__ W2r,
                                 const float* __restrict__ Wc,
                                 const float* __restrict__ bc) {
    __shared__ int s_is64;
    int t = threadIdx.x;
    if (t == 0) s_is64 = sniff64(ei);
    __syncthreads();
    int is64 = s_is64;

    if (blockIdx.x == 0) {
        if (t < 128) {                   // fold W2l@Wc, W2r@Wc
            int k = t >> 1, c = t & 1;
            float s = 0.f, sr = 0.f;
#pragma unroll
            for (int m = 0; m < 64; m++) {
                float w = Wc[m * 2 + c];
                s  += W2l[k * 64 + m] * w;
                sr += W2r[k * 64 + m] * w;
            }
            g_W2lc[k * 2 + c] = s;
            g_W2rc[k * 2 + c] = sr;
        }
        if (t < 2) {
            float sb = 0.f;
            for (int m = 0; m < 64; m++) sb += b2[m] * Wc[m * 2 + t];
            g_bc2[t] = sb + bc[t];
        }
        // pack B fragments: B[k][n] = k<64 ? W1l[k][n] : W1r[k-64][n]
        // frag (kstep s, ntile nt, lane l): {B[s*8+tg][nt*8+gr], B[s*8+tg+4][nt*8+gr]}
#pragma unroll
        for (int q = 0; q < 16; q++) {
            int idx = t * 16 + q;                 // 0..4095
            int lane = idx & 31;
            int nt   = (idx >> 5) & 7;
            int s    = idx >> 8;
            int gr = lane >> 2, tg = lane & 3;
            int k0 = s * 8 + tg, k1 = k0 + 4;
            int n  = nt * 8 + gr;
            float v0 = (k0 < 64) ? W1l[k0 * 64 + n] : W1r[(k0 - 64) * 64 + n];
            float v1 = (k1 < 64) ? W1l[k1 * 64 + n] : W1r[(k1 - 64) * 64 + n];
            float2 o;
            o.x = __uint_as_float(tf32r(v0));
            o.y = __uint_as_float(tf32r(v1));
            g_Wfrag[idx] = o;
        }
    }

    int base = (blockIdx.x * blockDim.x + t) * 4;
#pragma unroll
    for (int u = 0; u < 4; u++) {
        int e = base + u;
        if (e < E) {
            int dst = edge_val(ei, is64, E + e);
            if ((unsigned)dst < (unsigned)nn)
                atomicAdd(&g_cnt[dst], 1);
        }
    }
}

// ---------------------------------------------------------------- K2: single-pass scan
__global__ void sage_scan_kernel(int n, int nb) {
    __shared__ int wsum[32];
    __shared__ int pre_s;
    int b = blockIdx.x;
    int t = threadIdx.x;
    int lane = t & 31, wid = t >> 5;
    int i = b * 1024 + t;
    int v = (i < n) ? g_cnt[i] : 0;
    int x = v;
#pragma unroll
    for (int d = 1; d < 32; d <<= 1) {
        int y = __shfl_up_sync(0xffffffffu, x, d);
        if (lane >= d) x += y;
    }
    if (lane == 31) wsum[wid] = x;
    __syncthreads();
    if (wid == 0) {
        int w = wsum[lane];
        int xw = w;
#pragma unroll
        for (int d = 1; d < 32; d <<= 1) {
            int y = __shfl_up_sync(0xffffffffu, xw, d);
            if (lane >= d) xw += y;
        }
        wsum[lane] = xw;
    }
    __syncthreads();
    int total = wsum[31];
    if (t == 0) {
        pre_s = 0;
        g_bsum[b] = total;
        __threadfence();
        g_bflag[b] = 1;
    }
    __syncthreads();
    if (t < b) {
        while (g_bflag[t] == 0) {}
        __threadfence();
        atomicAdd(&pre_s, g_bsum[t]);
    }
    __syncthreads();
    int pre = pre_s;
    int wexcl = (wid == 0) ? 0 : wsum[wid - 1];
    if (i < n) {
        int o = pre + (x - v) + wexcl;
        g_off[i] = o;
        g_cur[i] = o;
    }
    if (b == nb - 1 && t == 0) g_off[n] = pre + total;
}

// ---------------------------------------------------------------- K3: fill
__global__ void sage_fill_kernel(const int* __restrict__ ei, int E, int nn) {
    __shared__ int s_is64;
    if (threadIdx.x == 0) s_is64 = sniff64(ei);
    __syncthreads();
    int is64 = s_is64;
    int base = (blockIdx.x * blockDim.x + threadIdx.x) * 4;
#pragma unroll
    for (int u = 0; u < 4; u++) {
        int e = base + u;
        if (e < E) {
            int src = edge_val(ei, is64, e);
            int dst = edge_val(ei, is64, E + e);
            if ((unsigned)dst < (unsigned)nn && (unsigned)src < (unsigned)nn) {
                int p = atomicAdd(&g_cur[dst], 1);
                if ((unsigned)p < (unsigned)EMAX)
                    g_csr[p] = src;
            }
        }
    }
}

// ---------------------------------------------------------------- K4: fused gather + tf32 MMA + epilogue
// Gather (as R12, proven): 16 thr/node, lane c owns float4 chunk c; stores
// tf32-rounded bits into S[m][k] (k<64: neighbor mean, k>=64: x row).
// GEMM: D[64x64] = S[64x128] @ Bfrag via mma.m16n8k8.tf32.
// 8 warps: mt = w&3 (16 m rows), nh = w>>2 (32 n cols). Epilogue folds
// layer2+classifier per 32-col half; halves combined through smem.
__global__ void __launch_bounds__(256, 5) sage_layer1_kernel(
        const float* __restrict__ x,
        const float* __restrict__ b1,
        int nn) {
    __shared__ unsigned S_u[64 * S_STRIDE];   // tf32 bits, [m][k] + pad
    __shared__ float4 part[2][64];            // per-n-half partial (t0,t1,r0,r1)
    __shared__ float b1_s[64];
    __shared__ float Wlc_s[128];
    __shared__ float Wrc_s[128];

    int tid = threadIdx.x;
    if (tid < 64)  b1_s[tid] = b1[tid];
    if (tid >= 64 && tid < 192) {
        Wlc_s[tid - 64] = g_W2lc[tid - 64];
        Wrc_s[tid - 64] = g_W2rc[tid - 64];
    }

    int m0 = blockIdx.x * 64;
    {   // ---- gather phase: 4 passes x 16 nodes, 16 threads per node
        int c  = tid & 15;          // float4 chunk of the 64-float row
        int pn = tid >> 4;          // 0..15
#pragma unroll 1
        for (int p = 0; p < 4; p++) {
            int m  = p * 16 + pn;
            int gm = m0 + m;
            float4 acc = make_float4(0.f, 0.f, 0.f, 0.f);
            float4 xr  = make_float4(0.f, 0.f, 0.f, 0.f);
            if (gm < nn) {
                xr = __ldg((const float4*)(x + (size_t)gm * 64) + c);
                int s0 = g_off[gm], s1 = g_off[gm + 1];
                int e = s0;
                for (; e + 4 <= s1; e += 4) {
                    int i0 = g_csr[e + 0], i1 = g_csr[e + 1];
                    int i2 = g_csr[e + 2], i3 = g_csr[e + 3];
                    float4 v0 = __ldg((const float4*)(x + (size_t)i0 * 64) + c);
                    float4 v1 = __ldg((const float4*)(x + (size_t)i1 * 64) + c);
                    float4 v2 = __ldg((const float4*)(x + (size_t)i2 * 64) + c);
                    float4 v3 = __ldg((const float4*)(x + (size_t)i3 * 64) + c);
                    acc.x += v0.x + v1.x + v2.x + v3.x;
                    acc.y += v0.y + v1.y + v2.y + v3.y;
                    acc.z += v0.z + v1.z + v2.z + v3.z;
                    acc.w += v0.w + v1.w + v2.w + v3.w;
                }
                for (; e < s1; e++) {
                    float4 v = __ldg((const float4*)(x + (size_t)g_csr[e] * 64) + c);
                    acc.x += v.x; acc.y += v.y; acc.z += v.z; acc.w += v.w;
                }
                float inv = 1.0f / fmaxf((float)(s1 - s0), 1.0f);
                acc.x *= inv; acc.y *= inv; acc.z *= inv; acc.w *= inv;
            }
            uint4 ua, ux;
            ua.x = tf32r(acc.x); ua.y = tf32r(acc.y);
            ua.z = tf32r(acc.z); ua.w = tf32r(acc.w);
            ux.x = tf32r(xr.x);  ux.y = tf32r(xr.y);
            ux.z = tf32r(xr.z);  ux.w = tf32r(xr.w);
            *(uint4*)&S_u[m * S_STRIDE + c * 4]      = ua;   // A part: k 0..63
            *(uint4*)&S_u[m * S_STRIDE + 64 + c * 4] = ux;   // X part: k 64..127
        }
    }
    __syncthreads();

    // ---- MMA phase
    int lane = tid & 31;
    int w    = tid >> 5;
    int mt   = w & 3;            // m-tile (16 rows)
    int nh   = w >> 2;           // n-half (32 cols)
    int gr = lane >> 2, tg = lane & 3;

    float acc[4][4];
#pragma unroll
    for (int j = 0; j < 4; j++)
#pragma unroll
        for (int q = 0; q < 4; q++) acc[j][q] = 0.f;

    const float2* __restrict__ wf = g_Wfrag;
    int rowA = (mt * 16 + gr) * S_STRIDE;
#pragma unroll 4
    for (int s = 0; s < 16; s++) {
        int ka = s * 8 + tg;
        unsigned a0 = S_u[rowA + ka];
        unsigned a1 = S_u[rowA + 8 * S_STRIDE + ka];
        unsigned a2 = S_u[rowA + ka + 4];
        unsigned a3 = S_u[rowA + 8 * S_STRIDE + ka + 4];
#pragma unroll
        for (int j = 0; j < 4; j++) {
            int nt = nh * 4 + j;
            float2 b = __ldg(&wf[(s * 8 + nt) * 32 + lane]);
            mma_tf32(acc[j], a0, a1, a2, a3,
                     __float_as_uint(b.x), __float_as_uint(b.y));
        }
    }

    // ---- epilogue: relu + fold layer2/classifier over this warp's 32 cols
    float tA0 = 0.f, tA1 = 0.f, rA0 = 0.f, rA1 = 0.f;   // row gr
    float tB0 = 0.f, tB1 = 0.f, rB0 = 0.f, rB1 = 0.f;   // row gr+8
#pragma unroll
    for (int j = 0; j < 4; j++) {
        int c0 = nh * 32 + j * 8 + 2 * tg;
        int c1 = c0 + 1;
        float h00 = fmaxf(acc[j][0] + b1_s[c0], 0.f);
        float h01 = fmaxf(acc[j][1] + b1_s[c1], 0.f);
        float h10 = fmaxf(acc[j][2] + b1_s[c0], 0.f);
        float h11 = fmaxf(acc[j][3] + b1_s[c1], 0.f);
        tA0 += h00 * Wlc_s[c0 * 2 + 0] + h01 * Wlc_s[c1 * 2 + 0];
        tA1 += h00 * Wlc_s[c0 * 2 + 1] + h01 * Wlc_s[c1 * 2 + 1];
        rA0 += h00 * Wrc_s[c0 * 2 + 0] + h01 * Wrc_s[c1 * 2 + 0];
        rA1 += h00 * Wrc_s[c0 * 2 + 1] + h01 * Wrc_s[c1 * 2 + 1];
        tB0 += h10 * Wlc_s[c0 * 2 + 0] + h11 * Wlc_s[c1 * 2 + 0];
        tB1 += h10 * Wlc_s[c0 * 2 + 1] + h11 * Wlc_s[c1 * 2 + 1];
        rB0 += h10 * Wrc_s[c0 * 2 + 0] + h11 * Wrc_s[c1 * 2 + 0];
        rB1 += h10 * Wrc_s[c0 * 2 + 1] + h11 * Wrc_s[c1 * 2 + 1];
    }
#pragma unroll
    for (int d = 1; d <= 2; d <<= 1) {   // reduce across the 4 tg lanes
        tA0 += __shfl_xor_sync(0xffffffffu, tA0, d);
        tA1 += __shfl_xor_sync(0xffffffffu, tA1, d);
        rA0 += __shfl_xor_sync(0xffffffffu, rA0, d);
        rA1 += __shfl_xor_sync(0xffffffffu, rA1, d);
        tB0 += __shfl_xor_sync(0xffffffffu, tB0, d);
        tB1 += __shfl_xor_sync(0xffffffffu, tB1, d);
        rB0 += __shfl_xor_sync(0xffffffffu, rB0, d);
        rB1 += __shfl_xor_sync(0xffffffffu, rB1, d);
    }
    if (tg == 0) {
        part[nh][mt * 16 + gr]     = make_float4(tA0, tA1, rA0, rA1);
        part[nh][mt * 16 + gr + 8] = make_float4(tB0, tB1, rB0, rB1);
    }
    __syncthreads();

    if (tid < 64) {
        float4 u = part[0][tid];
        float4 v = part[1][tid];
        int gm = m0 + tid;
        if (gm < nn) {
            g_t[gm] = make_float2(u.x + v.x, u.y + v.y);
            g_r[gm] = make_float2(u.z + v.z, u.w + v.w);
        }
    }
}

// ---------------------------------------------------------------- K5: final (+ state reset)
__global__ void sage_final_kernel(float2* __restrict__ out, int nn) {
    int i = blockIdx.x * blockDim.x + threadIdx.x;
    if (blockIdx.x == 0 && threadIdx.x < NB_SCAN) g_bflag[threadIdx.x] = 0;
    if (i >= nn) return;
    g_cnt[i] = 0;                            // restore for next replay
    int s0 = g_off[i], s1 = g_off[i + 1];
    float a0 = 0.f, a1 = 0.f, b0 = 0.f, b1v = 0.f;
    int e = s0;
    for (; e + 1 < s1; e += 2) {
        float2 vA = g_t[g_csr[e]];
        float2 vB = g_t[g_csr[e + 1]];
        a0 += vA.x; a1 += vA.y;
        b0 += vB.x; b1v += vB.y;
    }
    if (e < s1) {
        float2 vA = g_t[g_csr[e]];
        a0 += vA.x; a1 += vA.y;
    }
    float inv = 1.0f / fmaxf((float)(s1 - s0), 1.0f);
    float2 rv = g_r[i];
    out[i] = make_float2((a0 + b0) * inv + rv.x + g_bc2[0],
                         (a1 + b1v) * inv + rv.y + g_bc2[1]);
}

// ---------------------------------------------------------------- launch
extern "C" void kernel_launch(void* const* d_in, const int* in_sizes, int n_in,
                              void* d_out, int out_size) {
    const float* x   = (const float*)d_in[0];
    const int*   ei  = (const int*)d_in[1];     // int32 or int64 (auto-detected)
    const float* W1l = (const float*)d_in[2];
    const float* b1  = (const float*)d_in[3];
    const float* W1r = (const float*)d_in[4];
    const float* W2l = (const float*)d_in[5];
    const float* b2  = (const float*)d_in[6];
    const float* W2r = (const float*)d_in[7];
    const float* Wc  = (const float*)d_in[8];
    const float* bc  = (const float*)d_in[9];

    int nn = in_sizes[0] / 64;
    int E  = in_sizes[1] / 2;
    if (nn > NMAX) nn = NMAX;
    if (E > EMAX)  E = EMAX;
    int nb = (nn + 1023) / 1024;

    sage_hist_kernel<<<(E / 4 + 255) / 256, 256>>>(ei, E, nn, W1l, W1r,
                                                   W2l, b2, W2r, Wc, bc);
    sage_scan_kernel<<<nb, 1024>>>(nn, nb);
    sage_fill_kernel<<<(E / 4 + 255) / 256, 256>>>(ei, E, nn);
    sage_layer1_kernel<<<(nn + 63) / 64, 256>>>(x, b1, nn);             // launch #4
    sage_final_kernel<<<(nn + 255) / 256, 256>>>((float2*)d_out, nn);
}

// round 15
// speedup vs baseline: 2.1793x; 1.0586x over previous
#include <cuda_runtime.h>

// GraphSAGE on GB300 — 5 kernels (layer1 at launch #4 for ncu):
//   K1 hist:  cnt[dst]++ ; block0 folds W2l@Wc/W2r@Wc/bc2 AND packs
//             [W1l;W1r] into tf32 mma B-fragment order (g_Wfrag)
//   K2 scan:  single-pass exclusive scan (decoupled lookback)
//   K3 fill:  csr[cur[dst]++] = src
//   K4 layer1 FUSED: warp-cooperative gather (16 lanes/node: one coalesced
//             csr batch-load + width-16 shuffle broadcast with PER-HALF
//             member mask -> 16 independent x loads per batch, MLP=16)
//             into an [m][k] tf32 smem tile, then mma.sync.m16n8k8.tf32,
//             folded layer2+classifier epilogue.
//   K5 final: out[i] = mean_{e:dst=i} t[src[e]] + r[i] + bc2; reset state

#define NMAX 100000
#define EMAX 1600000
#define NB_SCAN ((NMAX + 1023) / 1024)   // 98
#define S_STRIDE 132                      // 128 k + 4 pad (conflict-free frags)

__device__ float2 g_t[NMAX];
__device__ float2 g_r[NMAX];
__device__ int    g_cnt[NMAX];           // zero-init; re-zeroed by K5
__device__ int    g_off[NMAX + 1];
__device__ int    g_cur[NMAX];
__device__ int    g_csr[EMAX];
__device__ int    g_bsum[NB_SCAN];
__device__ volatile int g_bflag[NB_SCAN]; // zero-init; re-zeroed by K5
__device__ float2 g_Wfrag[16 * 8 * 32];   // [kstep][ntile][lane] tf32 B frags
__device__ float  g_W2lc[128];
__device__ float  g_W2rc[128];
__device__ float  g_bc2[2];

__device__ __forceinline__ int edge_val(const int* __restrict__ w, int is64, int idx) {
    return is64 ? w[2 * idx] : w[idx];   // int64 little-endian low word, or int32
}
__device__ __forceinline__ int sniff64(const int* __restrict__ w) {
    int odd = 0;
#pragma unroll
    for (int j = 1; j < 64; j += 2) odd |= w[j];
    return odd == 0;
}
__device__ __forceinline__ unsigned tf32r(float f) {
    unsigned u;
    asm("cvt.rna.tf32.f32 %0, %1;" : "=r"(u) : "f"(f));
    return u;
}
__device__ __forceinline__ void mma_tf32(float* c, unsigned a0, unsigned a1,
                                         unsigned a2, unsigned a3,
                                         unsigned b0, unsigned b1) {
    asm("mma.sync.aligned.m16n8k8.row.col.f32.tf32.tf32.f32 "
        "{%0,%1,%2,%3}, {%4,%5,%6,%7}, {%8,%9}, {%0,%1,%2,%3};"
        : "+f"(c[0]), "+f"(c[1]), "+f"(c[2]), "+f"(c[3])
        : "r"(a0), "r"(a1), "r"(a2), "r"(a3), "r"(b0), "r"(b1));
}

// ---------------------------------------------------------------- K1: hist + fold + Wfrag pack
__global__ void sage_hist_kernel(const int* __restrict__ ei, int E, int nn,
                                 const float* __restrict__ W1l,
                                 const float* __restrict__ W1r,
                                 const float* __restrict__ W2l,
                                 const float* __restrict__ b2,
                                 const float* __restrict__ W2r,
                                 const float* __restrict__ Wc,
                                 const float* __restrict__ bc) {
    __shared__ int s_is64;
    int t = threadIdx.x;
    if (t == 0) s_is64 = sniff64(ei);
    __syncthreads();
    int is64 = s_is64;

    if (blockIdx.x == 0) {
        if (t < 128) {                   // fold W2l@Wc, W2r@Wc
            int k = t >> 1, c = t & 1;
            float s = 0.f, sr = 0.f;
#pragma unroll
            for (int m = 0; m < 64; m++) {
                float w = Wc[m * 2 + c];
                s  += W2l[k * 64 + m] * w;
                sr += W2r[k * 64 + m] * w;
            }
            g_W2lc[k * 2 + c] = s;
            g_W2rc[k * 2 + c] = sr;
        }
        if (t < 2) {
            float sb = 0.f;
            for (int m = 0; m < 64; m++) sb += b2[m] * Wc[m * 2 + t];
            g_bc2[t] = sb + bc[t];
        }
        // pack B fragments: B[k][n] = k<64 ? W1l[k][n] : W1r[k-64][n]
        // frag (kstep s, ntile nt, lane l): {B[s*8+tg][nt*8+gr], B[s*8+tg+4][nt*8+gr]}
#pragma unroll
        for (int q = 0; q < 16; q++) {
            int idx = t * 16 + q;                 // 0..4095
            int lane = idx & 31;
            int nt   = (idx >> 5) & 7;
            int s    = idx >> 8;
            int gr = lane >> 2, tg = lane & 3;
            int k0 = s * 8 + tg, k1 = k0 + 4;
            int n  = nt * 8 + gr;
            float v0 = (k0 < 64) ? W1l[k0 * 64 + n] : W1r[(k0 - 64) * 64 + n];
            float v1 = (k1 < 64) ? W1l[k1 * 64 + n] : W1r[(k1 - 64) * 64 + n];
            float2 o;
            o.x = __uint_as_float(tf32r(v0));
            o.y = __uint_as_float(tf32r(v1));
            g_Wfrag[idx] = o;
        }
    }

    int base = (blockIdx.x * blockDim.x + t) * 4;
#pragma unroll
    for (int u = 0; u < 4; u++) {
        int e = base + u;
        if (e < E) {
            int dst = edge_val(ei, is64, E + e);
            if ((unsigned)dst < (unsigned)nn)
                atomicAdd(&g_cnt[dst], 1);
        }
    }
}

// ---------------------------------------------------------------- K2: single-pass scan
__global__ void sage_scan_kernel(int n, int nb) {
    __shared__ int wsum[32];
    __shared__ int pre_s;
    int b = blockIdx.x;
    int t = threadIdx.x;
    int lane = t & 31, wid = t >> 5;
    int i = b * 1024 + t;
    int v = (i < n) ? g_cnt[i] : 0;
    int x = v;
#pragma unroll
    for (int d = 1; d < 32; d <<= 1) {
        int y = __shfl_up_sync(0xffffffffu, x, d);
        if (lane >= d) x += y;
    }
    if (lane == 31) wsum[wid] = x;
    __syncthreads();
    if (wid == 0) {
        int w = wsum[lane];
        int xw = w;
#pragma unroll
        for (int d = 1; d < 32; d <<= 1) {
            int y = __shfl_up_sync(0xffffffffu, xw, d);
            if (lane >= d) xw += y;
        }
        wsum[lane] = xw;
    }
    __syncthreads();
    int total = wsum[31];
    if (t == 0) {
        pre_s = 0;
        g_bsum[b] = total;
        __threadfence();
        g_bflag[b] = 1;
    }
    __syncthreads();
    if (t < b) {
        while (g_bflag[t] == 0) {}
        __threadfence();
        atomicAdd(&pre_s, g_bsum[t]);
    }
    __syncthreads();
    int pre = pre_s;
    int wexcl = (wid == 0) ? 0 : wsum[wid - 1];
    if (i < n) {
        int o = pre + (x - v) + wexcl;
        g_off[i] = o;
        g_cur[i] = o;
    }
    if (b == nb - 1 && t == 0) g_off[n] = pre + total;
}

// ---------------------------------------------------------------- K3: fill
__global__ void sage_fill_kernel(const int* __restrict__ ei, int E, int nn) {
    __shared__ int s_is64;
    if (threadIdx.x == 0) s_is64 = sniff64(ei);
    __syncthreads();
    int is64 = s_is64;
    int base = (blockIdx.x * blockDim.x + threadIdx.x) * 4;
#pragma unroll
    for (int u = 0; u < 4; u++) {
        int e = base + u;
        if (e < E) {
            int src = edge_val(ei, is64, e);
            int dst = edge_val(ei, is64, E + e);
            if ((unsigned)dst < (unsigned)nn && (unsigned)src < (unsigned)nn) {
                int p = atomicAdd(&g_cur[dst], 1);
                if ((unsigned)p < (unsigned)EMAX)
                    g_csr[p] = src;
            }
        }
    }
}

// ---------------------------------------------------------------- K4: fused gather + tf32 MMA + epilogue
// Gather: 16 lanes per node. Per 16-edge batch: lane c loads csr[e0+c]
// (coalesced 64B), width-16 shuffles (member mask = this half-warp ONLY,
// so differing trip counts between the two halves cannot deadlock)
// broadcast each index; each lane loads its float4 chunk -> 16 INDEPENDENT
// x loads per batch (MLP=16). tf32-rounded into S[m][k] (A|X concat k=128).
// GEMM: mma.m16n8k8.tf32, 8 warps (4 m-tiles x 2 n-halves); epilogue folds
// layer2+classifier; n-halves combined via smem.
__global__ void __launch_bounds__(256, 5) sage_layer1_kernel(
        const float* __restrict__ x,
        const float* __restrict__ b1,
        int nn) {
    __shared__ unsigned S_u[64 * S_STRIDE];   // tf32 bits, [m][k] + pad
    __shared__ float4 part[2][64];            // per-n-half partial (t0,t1,r0,r1)
    __shared__ float b1_s[64];
    __shared__ float Wlc_s[128];
    __shared__ float Wrc_s[128];

    int tid = threadIdx.x;
    if (tid < 64)  b1_s[tid] = b1[tid];
    if (tid >= 64 && tid < 192) {
        Wlc_s[tid - 64] = g_W2lc[tid - 64];
        Wrc_s[tid - 64] = g_W2rc[tid - 64];
    }

    int m0 = blockIdx.x * 64;
    {   // ---- gather phase: 4 passes x 16 nodes, 16 lanes per node
        int c  = tid & 15;          // float4 chunk; also lane-in-group
        int pn = tid >> 4;          // 0..15
        unsigned gmask = 0xFFFFu << (tid & 16);   // THIS half-warp only
#pragma unroll 1
        for (int p = 0; p < 4; p++) {
            int m  = p * 16 + pn;
            int gm = m0 + m;
            float4 acc = make_float4(0.f, 0.f, 0.f, 0.f);
            float4 xr  = make_float4(0.f, 0.f, 0.f, 0.f);
            if (gm < nn) {                       // group-uniform guard
                xr = __ldg((const float4*)(x + (size_t)gm * 64) + c);
                int s0 = g_off[gm], s1 = g_off[gm + 1];
                for (int e0 = s0; e0 < s1; e0 += 16) {
                    int my = e0 + c;
                    int idx = (my < s1) ? g_csr[my] : -1;   // coalesced 64B batch
#pragma unroll
                    for (int j = 0; j < 16; j++) {
                        int s = __shfl_sync(gmask, idx, j, 16);
                        if (s >= 0) {                        // uniform per group
                            float4 v = __ldg((const float4*)(x + (size_t)s * 64) + c);
                            acc.x += v.x; acc.y += v.y;
                            acc.z += v.z; acc.w += v.w;
                        }
                    }
                }
                float inv = 1.0f / fmaxf((float)(s1 - s0), 1.0f);
                acc.x *= inv; acc.y *= inv; acc.z *= inv; acc.w *= inv;
            }
            uint4 ua, ux;
            ua.x = tf32r(acc.x); ua.y = tf32r(acc.y);
            ua.z = tf32r(acc.z); ua.w = tf32r(acc.w);
            ux.x = tf32r(xr.x);  ux.y = tf32r(xr.y);
            ux.z = tf32r(xr.z);  ux.w = tf32r(xr.w);
            *(uint4*)&S_u[m * S_STRIDE + c * 4]      = ua;   // A part: k 0..63
            *(uint4*)&S_u[m * S_STRIDE + 64 + c * 4] = ux;   // X part: k 64..127
        }
    }
    __syncthreads();

    // ---- MMA phase
    int lane = tid & 31;
    int w    = tid >> 5;
    int mt   = w & 3;            // m-tile (16 rows)
    int nh   = w >> 2;           // n-half (32 cols)
    int gr = lane >> 2, tg = lane & 3;

    float acc[4][4];
#pragma unroll
    for (int j = 0; j < 4; j++)
#pragma unroll
        for (int q = 0; q < 4; q++) acc[j][q] = 0.f;

    const float2* __restrict__ wf = g_Wfrag;
    int rowA = (mt * 16 + gr) * S_STRIDE;
#pragma unroll 4
    for (int s = 0; s < 16; s++) {
        int ka = s * 8 + tg;
        unsigned a0 = S_u[rowA + ka];
        unsigned a1 = S_u[rowA + 8 * S_STRIDE + ka];
        unsigned a2 = S_u[rowA + ka + 4];
        unsigned a3 = S_u[rowA + 8 * S_STRIDE + ka + 4];
#pragma unroll
        for (int j = 0; j < 4; j++) {
            int nt = nh * 4 + j;
            float2 b = __ldg(&wf[(s * 8 + nt) * 32 + lane]);
            mma_tf32(acc[j], a0, a1, a2, a3,
                     __float_as_uint(b.x), __float_as_uint(b.y));
        }
    }

    // ---- epilogue: relu + fold layer2/classifier over this warp's 32 cols
    float tA0 = 0.f, tA1 = 0.f, rA0 = 0.f, rA1 = 0.f;   // row gr
    float tB0 = 0.f, tB1 = 0.f, rB0 = 0.f, rB1 = 0.f;   // row gr+8
#pragma unroll
    for (int j = 0; j < 4; j++) {
        int c0 = nh * 32 + j * 8 + 2 * tg;
        int c1 = c0 + 1;
        float h00 = fmaxf(acc[j][0] + b1_s[c0], 0.f);
        float h01 = fmaxf(acc[j][1] + b1_s[c1], 0.f);
        float h10 = fmaxf(acc[j][2] + b1_s[c0], 0.f);
        float h11 = fmaxf(acc[j][3] + b1_s[c1], 0.f);
        tA0 += h00 * Wlc_s[c0 * 2 + 0] + h01 * Wlc_s[c1 * 2 + 0];
        tA1 += h00 * Wlc_s[c0 * 2 + 1] + h01 * Wlc_s[c1 * 2 + 1];
        rA0 += h00 * Wrc_s[c0 * 2 + 0] + h01 * Wrc_s[c1 * 2 + 0];
        rA1 += h00 * Wrc_s[c0 * 2 + 1] + h01 * Wrc_s[c1 * 2 + 1];
        tB0 += h10 * Wlc_s[c0 * 2 + 0] + h11 * Wlc_s[c1 * 2 + 0];
        tB1 += h10 * Wlc_s[c0 * 2 + 1] + h11 * Wlc_s[c1 * 2 + 1];
        rB0 += h10 * Wrc_s[c0 * 2 + 0] + h11 * Wrc_s[c1 * 2 + 0];
        rB1 += h10 * Wrc_s[c0 * 2 + 1] + h11 * Wrc_s[c1 * 2 + 1];
    }
#pragma unroll
    for (int d = 1; d <= 2; d <<= 1) {   // reduce across the 4 tg lanes
        tA0 += __shfl_xor_sync(0xffffffffu, tA0, d);
        tA1 += __shfl_xor_sync(0xffffffffu, tA1, d);
        rA0 += __shfl_xor_sync(0xffffffffu, rA0, d);
        rA1 += __shfl_xor_sync(0xffffffffu, rA1, d);
        tB0 += __shfl_xor_sync(0xffffffffu, tB0, d);
        tB1 += __shfl_xor_sync(0xffffffffu, tB1, d);
        rB0 += __shfl_xor_sync(0xffffffffu, rB0, d);
        rB1 += __shfl_xor_sync(0xffffffffu, rB1, d);
    }
    if (tg == 0) {
        part[nh][mt * 16 + gr]     = make_float4(tA0, tA1, rA0, rA1);
        part[nh][mt * 16 + gr + 8] = make_float4(tB0, tB1, rB0, rB1);
    }
    __syncthreads();

    if (tid < 64) {
        float4 u = part[0][tid];
        float4 v = part[1][tid];
        int gm = m0 + tid;
        if (gm < nn) {
            g_t[gm] = make_float2(u.x + v.x, u.y + v.y);
            g_r[gm] = make_float2(u.z + v.z, u.w + v.w);
        }
    }
}

// ---------------------------------------------------------------- K5: final (+ state reset)
__global__ void sage_final_kernel(float2* __restrict__ out, int nn) {
    int i = blockIdx.x * blockDim.x + threadIdx.x;
    if (blockIdx.x == 0 && threadIdx.x < NB_SCAN) g_bflag[threadIdx.x] = 0;
    if (i >= nn) return;
    g_cnt[i] = 0;                            // restore for next replay
    int s0 = g_off[i], s1 = g_off[i + 1];
    float a0 = 0.f, a1 = 0.f, b0 = 0.f, b1v = 0.f;
    int e = s0;
    for (; e + 1 < s1; e += 2) {
        float2 vA = g_t[g_csr[e]];
        float2 vB = g_t[g_csr[e + 1]];
        a0 += vA.x; a1 += vA.y;
        b0 += vB.x; b1v += vB.y;
    }
    if (e < s1) {
        float2 vA = g_t[g_csr[e]];
        a0 += vA.x; a1 += vA.y;
    }
    float inv = 1.0f / fmaxf((float)(s1 - s0), 1.0f);
    float2 rv = g_r[i];
    out[i] = make_float2((a0 + b0) * inv + rv.x + g_bc2[0],
                         (a1 + b1v) * inv + rv.y + g_bc2[1]);
}

// ---------------------------------------------------------------- launch
extern "C" void kernel_launch(void* const* d_in, const int* in_sizes, int n_in,
                              void* d_out, int out_size) {
    const float* x   = (const float*)d_in[0];
    const int*   ei  = (const int*)d_in[1];     // int32 or int64 (auto-detected)
    const float* W1l = (const float*)d_in[2];
    const float* b1  = (const float*)d_in[3];
    const float* W1r = (const float*)d_in[4];
    const float* W2l = (const float*)d_in[5];
    const float* b2  = (const float*)d_in[6];
    const float* W2r = (const float*)d_in[7];
    const float* Wc  = (const float*)d_in[8];
    const float* bc  = (const float*)d_in[9];

    int nn = in_sizes[0] / 64;
    int E  = in_sizes[1] / 2;
    if (nn > NMAX) nn = NMAX;
    if (E > EMAX)  E = EMAX;
    int nb = (nn + 1023) / 1024;

    sage_hist_kernel<<<(E / 4 + 255) / 256, 256>>>(ei, E, nn, W1l, W1r,
                                                   W2l, b2, W2r, Wc, bc);
    sage_scan_kernel<<<nb, 1024>>>(nn, nb);
    sage_fill_kernel<<<(E / 4 + 255) / 256, 256>>>(ei, E, nn);
    sage_layer1_kernel<<<(nn + 63) / 64, 256>>>(x, b1, nn);             // launch #4
    sage_final_kernel<<<(nn + 255) / 256, 256>>>((float2*)d_out, nn);
}